// round 1
// baseline (speedup 1.0000x reference)
#include <cuda_runtime.h>

// KBestDetector: B=16384 batches, M=16 rx, S=8 streams, 16-QAM (NBPS=4), K=64.
// One CTA (256 threads) per batch.
//
// Pipeline per batch:
//  1) chol(S) 16x16 complex (warp 0)
//  2) forward-solve L\[h|y]  (one warp per rhs column)
//  3) G = ht^H ht, z = ht^H yt
//  4) order = argsort desc diag(G); permute; chol 8x8 -> R=C^H; ybar = C^{-1} z_p
//  5) K-best: layer7 -> 16 cands; layer6: 256->64; layers5..0: 1024->64
//     selection = adaptive 8-bit radix-select on float bits, children in regs
//  6) LLR via per-(layer,bit) mins over the final 64 candidates

#define FULLM 0xffffffffu

__global__ void __launch_bounds__(256) kbest_kernel(
    const float* __restrict__ g_yr, const float* __restrict__ g_yi,
    const float* __restrict__ g_hr, const float* __restrict__ g_hi,
    const float* __restrict__ g_sr, const float* __restrict__ g_si,
    const float* __restrict__ g_pr, const float* __restrict__ g_pi,
    float* __restrict__ g_out)
{
    const int b    = blockIdx.x;
    const int tid  = threadIdx.x;
    const int lane = tid & 31;
    const int wrp  = tid >> 5;

    __shared__ float2 Lsh[16][17];     // S, overwritten by its Cholesky L
    __shared__ float2 Hts[16][9];      // whitened h (cols 0..7) and y (col 8)
    __shared__ float2 Gsh[8][8];
    __shared__ float2 Csh[8][8];       // permuted Gram -> its Cholesky (R = C^H)
    __shared__ float2 Zsh[8];
    __shared__ float2 Ybar[8];
    __shared__ int    Order[8];
    __shared__ float2 Pts[16];
    __shared__ float    Cdist[2][64];
    __shared__ unsigned Csym[2][64];   // 4 bits per layer: sym(l) at bits [4l,4l+4)
    __shared__ float2 Pbase[64];       // ybar[l] - interference, per parent
    __shared__ unsigned Hist[256];
    __shared__ float  NewD[64];
    __shared__ int    NewI[64];
    __shared__ unsigned long long EqK[128];
    __shared__ int S_binfo;
    __shared__ int SelCnt;
    __shared__ int EqCnt;

    // ---------------- load ----------------
    Lsh[tid >> 4][tid & 15] = make_float2(g_sr[b*256 + tid], g_si[b*256 + tid]);
    if (tid < 128) Hts[tid >> 3][tid & 7] = make_float2(g_hr[b*128 + tid], g_hi[b*128 + tid]);
    if (tid < 16)  Hts[tid][8] = make_float2(g_yr[b*16 + tid], g_yi[b*16 + tid]);
    if (tid >= 128 && tid < 144) { int q = tid - 128; Pts[q] = make_float2(g_pr[q], g_pi[q]); }
    __syncthreads();

    // ---------------- Cholesky 16x16 complex (warp 0) ----------------
    if (wrp == 0) {
        #pragma unroll 1
        for (int jc = 0; jc < 16; jc++) {
            float sx = 0.f, sy = 0.f;
            if (lane >= jc && lane < 16) {
                float2 a0 = Lsh[lane][jc];
                sx = a0.x; sy = a0.y;
                for (int k = 0; k < jc; k++) {       // s -= L[i,k]*conj(L[jc,k])
                    float2 a = Lsh[lane][k], c = Lsh[jc][k];
                    sx -= a.x*c.x + a.y*c.y;
                    sy -= a.y*c.x - a.x*c.y;
                }
            }
            float dj = __shfl_sync(FULLM, sx, jc);
            float dl = sqrtf(dj);
            if (lane == jc) Lsh[lane][jc] = make_float2(dl, 0.f);
            else if (lane > jc && lane < 16) Lsh[lane][jc] = make_float2(sx/dl, sy/dl);
            __syncwarp();
        }
    }
    __syncthreads();

    // ---------------- forward solve L X = [h | y] (column sweeps, warp/rhs) ----
    for (int c = wrp; c < 9; c += 8) {
        #pragma unroll 1
        for (int i = 0; i < 16; i++) {
            float xr = 0.f, xi = 0.f;
            if (lane == i) {
                float2 v = Hts[i][c];
                float dd = Lsh[i][i].x;
                xr = v.x / dd; xi = v.y / dd;
                Hts[i][c] = make_float2(xr, xi);
            }
            xr = __shfl_sync(FULLM, xr, i);
            xi = __shfl_sync(FULLM, xi, i);
            if (lane > i && lane < 16) {
                float2 lij = Lsh[lane][i];
                float2 v = Hts[lane][c];
                v.x -= lij.x*xr - lij.y*xi;
                v.y -= lij.x*xi + lij.y*xr;
                Hts[lane][c] = v;
            }
            __syncwarp();
        }
    }
    __syncthreads();

    // ---------------- Gram G = ht^H ht, z = ht^H yt ----------------
    if (tid < 64) {
        int i = tid >> 3, j = tid & 7;
        float gx = 0.f, gy = 0.f;
        #pragma unroll
        for (int m = 0; m < 16; m++) {          // conj(a)*c
            float2 a = Hts[m][i], c = Hts[m][j];
            gx += a.x*c.x + a.y*c.y;
            gy += a.x*c.y - a.y*c.x;
        }
        Gsh[i][j] = make_float2(gx, gy);
    } else if (tid < 72) {
        int i = tid - 64;
        float gx = 0.f, gy = 0.f;
        #pragma unroll
        for (int m = 0; m < 16; m++) {
            float2 a = Hts[m][i], c = Hts[m][8];
            gx += a.x*c.x + a.y*c.y;
            gy += a.x*c.y - a.y*c.x;
        }
        Zsh[i] = make_float2(gx, gy);
    }
    __syncthreads();

    // ---------------- ordering (stable argsort of -norms) ----------------
    if (tid < 8) {
        float ni = Gsh[tid][tid].x;
        int rank = 0;
        #pragma unroll
        for (int j = 0; j < 8; j++) {
            float nj = Gsh[j][j].x;
            rank += (nj > ni) || (nj == ni && j < tid);
        }
        Order[rank] = tid;
    }
    __syncthreads();
    if (tid < 64) {
        int i = tid >> 3, j = tid & 7;
        Csh[i][j] = Gsh[Order[i]][Order[j]];
    } else if (tid < 72) {
        Ybar[tid - 64] = Zsh[Order[tid - 64]];
    }
    __syncthreads();

    // ---------------- Cholesky 8x8 of permuted Gram + solve C ybar = z_p -----
    if (wrp == 0) {
        #pragma unroll 1
        for (int jc = 0; jc < 8; jc++) {
            float sx = 0.f, sy = 0.f;
            if (lane >= jc && lane < 8) {
                float2 a0 = Csh[lane][jc]; sx = a0.x; sy = a0.y;
                for (int k = 0; k < jc; k++) {
                    float2 a = Csh[lane][k], c = Csh[jc][k];
                    sx -= a.x*c.x + a.y*c.y;
                    sy -= a.y*c.x - a.x*c.y;
                }
            }
            float dj = __shfl_sync(FULLM, sx, jc);
            float dl = sqrtf(dj);
            if (lane == jc) Csh[lane][jc] = make_float2(dl, 0.f);
            else if (lane > jc && lane < 8) Csh[lane][jc] = make_float2(sx/dl, sy/dl);
            __syncwarp();
        }
        #pragma unroll 1
        for (int i = 0; i < 8; i++) {
            float xr = 0.f, xi = 0.f;
            if (lane == i) {
                float2 v = Ybar[i];
                float dd = Csh[i][i].x;
                xr = v.x / dd; xi = v.y / dd;
                Ybar[i] = make_float2(xr, xi);
            }
            xr = __shfl_sync(FULLM, xr, i);
            xi = __shfl_sync(FULLM, xi, i);
            if (lane > i && lane < 8) {
                float2 lij = Csh[lane][i];
                float2 v = Ybar[lane];
                v.x -= lij.x*xr - lij.y*xi;
                v.y -= lij.x*xi + lij.y*xr;
                Ybar[lane] = v;
            }
            __syncwarp();
        }
    }
    __syncthreads();

    // ---------------- layer 7: 16 initial candidates ----------------
    int cur = 0;
    if (tid < 16) {
        float r77 = Csh[7][7].x;
        float2 p = Pts[tid];
        float rr = Ybar[7].x - r77*p.x;
        float ri = Ybar[7].y - r77*p.y;
        Cdist[0][tid] = rr*rr + ri*ri;
        Csym[0][tid] = (unsigned)tid << 28;
    }
    __syncthreads();

    // ---------------- layers 6..0 ----------------
    for (int l = 6; l >= 0; l--) {
        const int nP  = (l == 6) ? 16 : 64;
        const int cnt = (l == 6) ? 1  : 4;     // children per thread
        const int nxt = cur ^ 1;

        // per-parent base = ybar[l] - sum_{j>l} conj(C[j][l]) * pts[sym_j]
        if (tid < nP) {
            unsigned sym = Csym[cur][tid];
            float ir = 0.f, ii = 0.f;
            for (int j = l + 1; j < 8; j++) {
                int q = (sym >> (4*j)) & 15;
                float2 c = Csh[j][l];
                float2 p = Pts[q];
                ir += c.x*p.x + c.y*p.y;
                ii += c.x*p.y - c.y*p.x;
            }
            Pbase[tid] = make_float2(Ybar[l].x - ir, Ybar[l].y - ii);
        }
        __syncthreads();

        // children distances (registers only)
        const float rll = Csh[l][l].x;
        float    distr[4];
        unsigned bitsr[4];
        #pragma unroll
        for (int j = 0; j < 4; j++) {
            if (j < cnt) {
                int idx = (cnt == 4) ? (tid*4 + j) : tid;
                int p = idx >> 4, q = idx & 15;
                float2 bs = Pbase[p];
                float2 pq = Pts[q];
                float pd = Cdist[cur][p];
                float rr = fmaf(-rll, pq.x, bs.x);
                float ri = fmaf(-rll, pq.y, bs.y);
                float d  = fmaf(rr, rr, fmaf(ri, ri, pd));
                distr[j] = d;
                bitsr[j] = __float_as_uint(d);
            }
        }

        // adaptive radix select: find exact 64 smallest
        unsigned pref = 0u, maskp = 0u;
        int shift = 24, c_below = 0, mcrit = 0;
        #pragma unroll 1
        for (int lev = 0; lev < 4; lev++) {
            __syncthreads();
            Hist[tid] = 0u;
            __syncthreads();
            #pragma unroll
            for (int j = 0; j < 4; j++) {
                if (j < cnt) {
                    unsigned bb = bitsr[j];
                    if ((bb & maskp) == pref)
                        atomicAdd(&Hist[(bb >> shift) & 255u], 1u);
                }
            }
            __syncthreads();
            if (tid < 32) {
                int ssum = 0;
                #pragma unroll
                for (int k = 0; k < 8; k++) ssum += (int)Hist[tid*8 + k];
                int incl = ssum;
                #pragma unroll
                for (int off = 1; off < 32; off <<= 1) {
                    int v = __shfl_up_sync(FULLM, incl, off);
                    if (lane >= off) incl += v;
                }
                int excl = incl - ssum;
                int target = 63 - c_below;
                if (excl <= target && target < incl) {
                    int cum = excl, bsel = tid*8;
                    #pragma unroll
                    for (int k = 0; k < 8; k++) {
                        int h = (int)Hist[tid*8 + k];
                        if (target < cum + h) { bsel = tid*8 + k; break; }
                        cum += h;
                    }
                    S_binfo = (bsel << 16) | cum;
                }
            }
            __syncthreads();
            int info = S_binfo;
            int bsel = info >> 16;
            c_below += info & 0xffff;
            mcrit = (int)Hist[bsel];
            pref  |= (unsigned)bsel << shift;
            maskp |= 255u << shift;
            if (mcrit <= 32 || shift == 0) break;
            shift -= 8;
        }

        if (tid == 0) { SelCnt = 0; EqCnt = 0; }
        __syncthreads();

        // compaction: strictly-below goes straight in; critical-bin elements
        // are ranked by (bits, idx) to exactly match top_k tie-breaking.
        #pragma unroll
        for (int j = 0; j < 4; j++) {
            if (j < cnt) {
                unsigned bb = bitsr[j];
                int idx = (cnt == 4) ? (tid*4 + j) : tid;
                if (bb < pref) {
                    int pos = atomicAdd(&SelCnt, 1);
                    NewD[pos] = distr[j];
                    NewI[pos] = idx;
                } else if ((bb & maskp) == pref) {
                    int e = atomicAdd(&EqCnt, 1);
                    if (e < 128) EqK[e] = (((unsigned long long)bb) << 10) | (unsigned)idx;
                }
            }
        }
        __syncthreads();
        {
            int need = 64 - c_below;
            int mm = EqCnt < 128 ? EqCnt : 128;
            if (tid < mm) {
                unsigned long long mykey = EqK[tid];
                int rank = 0;
                for (int j = 0; j < mm; j++) rank += (EqK[j] < mykey);
                if (rank < need) {
                    NewD[c_below + rank] = __uint_as_float((unsigned)(mykey >> 10));
                    NewI[c_below + rank] = (int)(mykey & 1023ull);
                }
            }
        }
        __syncthreads();

        if (tid < 64) {
            int idx = NewI[tid];
            int p = idx >> 4, q = idx & 15;
            Cdist[nxt][tid] = NewD[tid];
            Csym[nxt][tid]  = Csym[cur][p] | ((unsigned)q << (4*l));
        }
        __syncthreads();
        cur = nxt;
    }

    // ---------------- LLR ----------------
    if (tid < 32) {
        int l = tid >> 2, j = tid & 3;
        float d0 = 1000000000.0f, d1 = 1000000000.0f;
        for (int k = 0; k < 64; k++) {
            float d = Cdist[cur][k];
            int q = (int)((Csym[cur][k] >> (4*l)) & 15u);
            if ((q >> (3 - j)) & 1) d1 = fminf(d1, d);
            else                    d0 = fminf(d0, d);
        }
        float llr = fminf(fmaxf(d0 - d1, -20.f), 20.f);
        g_out[b*32 + Order[l]*4 + j] = llr;
    }
}

extern "C" void kernel_launch(void* const* d_in, const int* in_sizes, int n_in,
                              void* d_out, int out_size)
{
    const float* yr = (const float*)d_in[0];
    const float* yi = (const float*)d_in[1];
    const float* hr = (const float*)d_in[2];
    const float* hi = (const float*)d_in[3];
    const float* sr = (const float*)d_in[4];
    const float* si = (const float*)d_in[5];
    const float* pr = (const float*)d_in[6];
    const float* pi = (const float*)d_in[7];
    int B = in_sizes[0] / 16;
    kbest_kernel<<<B, 256>>>(yr, yi, hr, hi, sr, si, pr, pi, (float*)d_out);
}

// round 2
// speedup vs baseline: 1.2921x; 1.2921x over previous
#include <cuda_runtime.h>

// KBestDetector: B=16384, M=16 rx, S=8 streams, 16-QAM (NBPS=4), K=64.
// One CTA (128 threads) per batch, 8 children/thread in the K-best loop.
//
//  1) chol(S) 16x16 complex (warp 0)
//  2) forward-solve L\[h|y]  (warp per rhs column, round-robin)
//  3) G = ht^H ht, z = ht^H yt
//  4) order by diag(G) desc; permute; chol 8x8 -> R=C^H; ybar = C^{-1} z_p
//  5) K-best layers: separable (4x4 PAM) child distances; exact top-64 via
//     adaptive fixed-point histogram select (monotone key, exact tie cleanup)
//  6) LLR mins over final 64 candidates

#define FULLM 0xffffffffu

__global__ void __launch_bounds__(128) kbest_kernel(
    const float* __restrict__ g_yr, const float* __restrict__ g_yi,
    const float* __restrict__ g_hr, const float* __restrict__ g_hi,
    const float* __restrict__ g_sr, const float* __restrict__ g_si,
    const float* __restrict__ g_pr, const float* __restrict__ g_pi,
    float* __restrict__ g_out)
{
    const int b    = blockIdx.x;
    const int tid  = threadIdx.x;
    const int lane = tid & 31;
    const int wrp  = tid >> 5;

    __shared__ float2 Lsh[16][17];     // S -> its Cholesky L
    __shared__ float2 Hts[16][9];      // whitened h (cols 0..7) and y (col 8)
    __shared__ float2 Gsh[8][8];
    __shared__ float2 Csh[8][8];       // permuted Gram -> Cholesky (R = C^H)
    __shared__ float2 Zsh[8];
    __shared__ float2 Ybar[8];
    __shared__ int    Order[8];
    __shared__ float2 Pts[16];
    __shared__ float    Cdist[2][64];
    __shared__ unsigned Csym[2][64];   // 4 bits/layer: sym(l) at bits [4l,4l+4)
    __shared__ float  Pr[64][4];       // pd + (br - r*pam_a)^2
    __shared__ float  Pi2[64][4];      // (bi - r*pam_b)^2
    __shared__ unsigned Hist[256];
    __shared__ unsigned long long EqK[128];
    __shared__ float  WMin[4], WMax[4];
    __shared__ int S_binfo;
    __shared__ int SelCnt;
    __shared__ int EqCnt;

    // ---------------- load ----------------
    #pragma unroll
    for (int t = tid; t < 256; t += 128)
        Lsh[t >> 4][t & 15] = make_float2(g_sr[b*256 + t], g_si[b*256 + t]);
    Hts[tid >> 3][tid & 7] = make_float2(g_hr[b*128 + tid], g_hi[b*128 + tid]);
    if (tid < 16)  Hts[tid][8] = make_float2(g_yr[b*16 + tid], g_yi[b*16 + tid]);
    if (tid >= 112) { int q = tid - 112; Pts[q] = make_float2(g_pr[q], g_pi[q]); }
    __syncthreads();

    // ---------------- Cholesky 16x16 complex (warp 0) ----------------
    if (wrp == 0) {
        #pragma unroll 1
        for (int jc = 0; jc < 16; jc++) {
            float sx = 0.f, sy = 0.f;
            if (lane >= jc && lane < 16) {
                float2 a0 = Lsh[lane][jc];
                sx = a0.x; sy = a0.y;
                for (int k = 0; k < jc; k++) {       // s -= L[i,k]*conj(L[jc,k])
                    float2 a = Lsh[lane][k], c = Lsh[jc][k];
                    sx -= a.x*c.x + a.y*c.y;
                    sy -= a.y*c.x - a.x*c.y;
                }
            }
            float dj = __shfl_sync(FULLM, sx, jc);
            float dl = sqrtf(dj);
            if (lane == jc) Lsh[lane][jc] = make_float2(dl, 0.f);
            else if (lane > jc && lane < 16) Lsh[lane][jc] = make_float2(sx/dl, sy/dl);
            __syncwarp();
        }
    }
    __syncthreads();

    // ---------------- forward solve L X = [h | y] ----------------
    for (int c = wrp; c < 9; c += 4) {
        #pragma unroll 1
        for (int i = 0; i < 16; i++) {
            float xr = 0.f, xi = 0.f;
            if (lane == i) {
                float2 v = Hts[i][c];
                float dd = Lsh[i][i].x;
                xr = v.x / dd; xi = v.y / dd;
                Hts[i][c] = make_float2(xr, xi);
            }
            xr = __shfl_sync(FULLM, xr, i);
            xi = __shfl_sync(FULLM, xi, i);
            if (lane > i && lane < 16) {
                float2 lij = Lsh[lane][i];
                float2 v = Hts[lane][c];
                v.x -= lij.x*xr - lij.y*xi;
                v.y -= lij.x*xi + lij.y*xr;
                Hts[lane][c] = v;
            }
            __syncwarp();
        }
    }
    __syncthreads();

    // ---------------- Gram G = ht^H ht, z = ht^H yt ----------------
    if (tid < 64) {
        int i = tid >> 3, j = tid & 7;
        float gx = 0.f, gy = 0.f;
        #pragma unroll
        for (int m = 0; m < 16; m++) {
            float2 a = Hts[m][i], c = Hts[m][j];
            gx += a.x*c.x + a.y*c.y;
            gy += a.x*c.y - a.y*c.x;
        }
        Gsh[i][j] = make_float2(gx, gy);
    } else if (tid < 72) {
        int i = tid - 64;
        float gx = 0.f, gy = 0.f;
        #pragma unroll
        for (int m = 0; m < 16; m++) {
            float2 a = Hts[m][i], c = Hts[m][8];
            gx += a.x*c.x + a.y*c.y;
            gy += a.x*c.y - a.y*c.x;
        }
        Zsh[i] = make_float2(gx, gy);
    }
    __syncthreads();

    // ---------------- ordering (stable argsort of -norms) ----------------
    if (tid < 8) {
        float ni = Gsh[tid][tid].x;
        int rank = 0;
        #pragma unroll
        for (int j = 0; j < 8; j++) {
            float nj = Gsh[j][j].x;
            rank += (nj > ni) || (nj == ni && j < tid);
        }
        Order[rank] = tid;
    }
    __syncthreads();
    if (tid < 64) {
        int i = tid >> 3, j = tid & 7;
        Csh[i][j] = Gsh[Order[i]][Order[j]];
    } else if (tid < 72) {
        Ybar[tid - 64] = Zsh[Order[tid - 64]];
    }
    __syncthreads();

    // ------------- Cholesky 8x8 of permuted Gram + solve C ybar = z_p ------
    if (wrp == 0) {
        #pragma unroll 1
        for (int jc = 0; jc < 8; jc++) {
            float sx = 0.f, sy = 0.f;
            if (lane >= jc && lane < 8) {
                float2 a0 = Csh[lane][jc]; sx = a0.x; sy = a0.y;
                for (int k = 0; k < jc; k++) {
                    float2 a = Csh[lane][k], c = Csh[jc][k];
                    sx -= a.x*c.x + a.y*c.y;
                    sy -= a.y*c.x - a.x*c.y;
                }
            }
            float dj = __shfl_sync(FULLM, sx, jc);
            float dl = sqrtf(dj);
            if (lane == jc) Csh[lane][jc] = make_float2(dl, 0.f);
            else if (lane > jc && lane < 8) Csh[lane][jc] = make_float2(sx/dl, sy/dl);
            __syncwarp();
        }
        #pragma unroll 1
        for (int i = 0; i < 8; i++) {
            float xr = 0.f, xi = 0.f;
            if (lane == i) {
                float2 v = Ybar[i];
                float dd = Csh[i][i].x;
                xr = v.x / dd; xi = v.y / dd;
                Ybar[i] = make_float2(xr, xi);
            }
            xr = __shfl_sync(FULLM, xr, i);
            xi = __shfl_sync(FULLM, xi, i);
            if (lane > i && lane < 8) {
                float2 lij = Csh[lane][i];
                float2 v = Ybar[lane];
                v.x -= lij.x*xr - lij.y*xi;
                v.y -= lij.x*xi + lij.y*xr;
                Ybar[lane] = v;
            }
            __syncwarp();
        }
    }
    __syncthreads();

    // ---------------- layer 7: 16 initial candidates ----------------
    int cur = 0;
    if (tid < 16) {
        float r77 = Csh[7][7].x;
        float2 p = Pts[tid];
        float rr = Ybar[7].x - r77*p.x;
        float ri = Ybar[7].y - r77*p.y;
        Cdist[0][tid] = rr*rr + ri*ri;
        Csym[0][tid] = (unsigned)tid << 28;
    }
    __syncthreads();

    // ---------------- layers 6..0 ----------------
    for (int l = 6; l >= 0; l--) {
        const int nP  = (l == 6) ? 16 : 64;
        const int cnt = (l == 6) ? 2  : 8;     // children per thread
        const int nxt = cur ^ 1;

        if (tid == 0) { SelCnt = 0; EqCnt = 0; }

        // per-parent separable distance tables
        if (tid < nP) {
            unsigned sym = Csym[cur][tid];
            float pd = Cdist[cur][tid];
            float ir = 0.f, ii = 0.f;
            for (int j = l + 1; j < 8; j++) {
                int q = (sym >> (4*j)) & 15;
                float2 c = Csh[j][l];
                float2 p = Pts[q];
                ir += c.x*p.x + c.y*p.y;
                ii += c.x*p.y - c.y*p.x;
            }
            float br = Ybar[l].x - ir;
            float bi = Ybar[l].y - ii;
            float rll = Csh[l][l].x;
            #pragma unroll
            for (int a = 0; a < 4; a++) {
                float pr = Pts[((a & 2) << 2) | ((a & 1) << 1)].x;
                float t = fmaf(-rll, pr, br);
                Pr[tid][a] = fmaf(t, t, pd);
            }
            #pragma unroll
            for (int bidx = 0; bidx < 4; bidx++) {
                float pii = Pts[((bidx & 2) << 1) | (bidx & 1)].y;
                float t = fmaf(-rll, pii, bi);
                Pi2[tid][bidx] = t * t;
            }
        }
        __syncthreads();

        // children distances (registers only) + min/max partials + hist zero
        float    distr[8];
        unsigned selm = 0u, actm = 0u;
        float mn = 1e30f, mx = -1e30f;
        #pragma unroll
        for (int j = 0; j < 8; j++) {
            if (j < cnt) {
                int idx = tid*cnt + j;
                int q = idx & 15;
                int p = idx >> 4;
                int a  = ((q >> 2) & 2) | ((q >> 1) & 1);
                int bb = ((q >> 1) & 2) | (q & 1);
                float d = Pr[p][a] + Pi2[p][bb];
                distr[j] = d;
                actm |= 1u << j;
                mn = fminf(mn, d);
                mx = fmaxf(mx, d);
            }
        }
        #pragma unroll
        for (int o = 16; o; o >>= 1) {
            mn = fminf(mn, __shfl_xor_sync(FULLM, mn, o));
            mx = fmaxf(mx, __shfl_xor_sync(FULLM, mx, o));
        }
        if (lane == 0) { WMin[wrp] = mn; WMax[wrp] = mx; }
        Hist[tid] = 0u; Hist[tid + 128] = 0u;
        __syncthreads();

        float lo = fminf(fminf(WMin[0], WMin[1]), fminf(WMin[2], WMin[3]));
        float hi = fmaxf(fmaxf(WMax[0], WMax[1]), fmaxf(WMax[2], WMax[3]));
        int c_sel = 0;

        // adaptive fixed-point select (monotone key; exact ties via EqK)
        #pragma unroll 1
        for (int lev = 0; ; lev++) {
            if (lev) { __syncthreads(); Hist[tid] = 0u; Hist[tid + 128] = 0u; __syncthreads(); }
            float scale = 256.f / (hi - lo);
            int binr[8];
            #pragma unroll
            for (int j = 0; j < 8; j++) {
                if (j < cnt && ((actm >> j) & 1)) {
                    int bn = (int)((distr[j] - lo) * scale);
                    bn = bn < 0 ? 0 : (bn > 255 ? 255 : bn);
                    binr[j] = bn;
                    atomicAdd(&Hist[bn], 1u);
                }
            }
            __syncthreads();
            if (wrp == 0) {
                int ssum = 0;
                #pragma unroll
                for (int k = 0; k < 8; k++) ssum += (int)Hist[lane*8 + k];
                int incl = ssum;
                #pragma unroll
                for (int off = 1; off < 32; off <<= 1) {
                    int v = __shfl_up_sync(FULLM, incl, off);
                    if (lane >= off) incl += v;
                }
                int excl = incl - ssum;
                int target = 63 - c_sel;
                if (excl <= target && target < incl) {
                    int cum = excl, bsel = lane*8;
                    #pragma unroll
                    for (int k = 0; k < 8; k++) {
                        int h = (int)Hist[lane*8 + k];
                        if (target < cum + h) { bsel = lane*8 + k; break; }
                        cum += h;
                    }
                    S_binfo = (bsel << 16) | cum;
                }
            }
            __syncthreads();
            int info = S_binfo;
            int cb = info >> 16;
            c_sel += info & 0xffff;
            int mcrit = (int)Hist[cb];
            #pragma unroll
            for (int j = 0; j < 8; j++) {
                if (j < cnt && ((actm >> j) & 1)) {
                    if (binr[j] < cb)      { selm |= 1u << j; actm &= ~(1u << j); }
                    else if (binr[j] > cb) { actm &= ~(1u << j); }
                }
            }
            if (mcrit <= 96 || lev == 3) break;
            float w = (hi - lo) * 0.00390625f;
            float nlo = fmaf((float)cb, w, lo);
            hi = nlo + w;
            lo = nlo;
        }

        // compaction: strictly-below straight in; critical set ranked exactly
        #pragma unroll
        for (int j = 0; j < 8; j++) {
            if (j < cnt) {
                int idx = tid*cnt + j;
                if ((selm >> j) & 1) {
                    int s = atomicAdd(&SelCnt, 1);
                    int p = idx >> 4, q = idx & 15;
                    Cdist[nxt][s] = distr[j];
                    Csym[nxt][s]  = Csym[cur][p] | ((unsigned)q << (4*l));
                } else if ((actm >> j) & 1) {
                    int e = atomicAdd(&EqCnt, 1);
                    if (e < 128)
                        EqK[e] = (((unsigned long long)__float_as_uint(distr[j])) << 10)
                               | (unsigned)idx;
                }
            }
        }
        __syncthreads();
        {
            int need = 64 - c_sel;
            int mm = EqCnt < 128 ? EqCnt : 128;
            if (tid < mm) {
                unsigned long long mykey = EqK[tid];
                int rank = 0;
                for (int j = 0; j < mm; j++) rank += (EqK[j] < mykey);
                if (rank < need) {
                    int s = c_sel + rank;
                    int idx = (int)(mykey & 1023ull);
                    int p = idx >> 4, q = idx & 15;
                    Cdist[nxt][s] = __uint_as_float((unsigned)(mykey >> 10));
                    Csym[nxt][s]  = Csym[cur][p] | ((unsigned)q << (4*l));
                }
            }
        }
        __syncthreads();
        cur = nxt;
    }

    // ---------------- LLR ----------------
    if (tid < 32) {
        int l = tid >> 2, j = tid & 3;
        float d0 = 1000000000.0f, d1 = 1000000000.0f;
        for (int k = 0; k < 64; k++) {
            float d = Cdist[cur][k];
            int q = (int)((Csym[cur][k] >> (4*l)) & 15u);
            if ((q >> (3 - j)) & 1) d1 = fminf(d1, d);
            else                    d0 = fminf(d0, d);
        }
        float llr = fminf(fmaxf(d0 - d1, -20.f), 20.f);
        g_out[b*32 + Order[l]*4 + j] = llr;
    }
}

extern "C" void kernel_launch(void* const* d_in, const int* in_sizes, int n_in,
                              void* d_out, int out_size)
{
    const float* yr = (const float*)d_in[0];
    const float* yi = (const float*)d_in[1];
    const float* hr = (const float*)d_in[2];
    const float* hi = (const float*)d_in[3];
    const float* sr = (const float*)d_in[4];
    const float* si = (const float*)d_in[5];
    const float* pr = (const float*)d_in[6];
    const float* pi = (const float*)d_in[7];
    int B = in_sizes[0] / 16;
    kbest_kernel<<<B, 128>>>(yr, yi, hr, hi, sr, si, pr, pi, (float*)d_out);
}

// round 3
// speedup vs baseline: 1.4452x; 1.1185x over previous
#include <cuda_runtime.h>

// KBestDetector: B=16384, M=16 rx, S=8 streams, 16-QAM (NBPS=4), K=64.
// One CTA (128 threads) per batch, 8 children/thread in the K-best loop.
//
//  1) chol(S) 16x16 complex (warp 0)
//  2) forward-solve L\[h|y]  (warp per rhs column, round-robin)
//  3) G = ht^H ht, z = ht^H yt
//  4) order by diag(G) desc; permute; chol 8x8 -> R=C^H; ybar = C^{-1} z_p
//  5) K-best layers: separable (4x4 PAM) child distances held in registers;
//     exact top-64 via adaptive 128-bin fixed-point select + exact tie cleanup;
//     ballot-scan compaction (no per-element same-address atomics)
//  6) LLR mins over final 64 candidates, parallel over 4 warps

#define FULLM 0xffffffffu

__global__ void __launch_bounds__(128, 10) kbest_kernel(
    const float* __restrict__ g_yr, const float* __restrict__ g_yi,
    const float* __restrict__ g_hr, const float* __restrict__ g_hi,
    const float* __restrict__ g_sr, const float* __restrict__ g_si,
    const float* __restrict__ g_pr, const float* __restrict__ g_pi,
    float* __restrict__ g_out)
{
    const int b    = blockIdx.x;
    const int tid  = threadIdx.x;
    const int lane = tid & 31;
    const int wrp  = tid >> 5;

    __shared__ float2 Lsh[16][17];     // S -> its Cholesky L
    __shared__ float2 Hts[16][9];      // whitened h (cols 0..7) and y (col 8)
    __shared__ float2 Gsh[8][8];
    __shared__ float2 Csh[8][8];       // permuted Gram -> Cholesky (R = C^H)
    __shared__ float2 Zsh[8];
    __shared__ float2 Ybar[8];
    __shared__ int    Order[8];
    __shared__ float2 Pts[16];
    __shared__ float    Cdist[2][64];
    __shared__ unsigned Csym[2][64];   // 4 bits/layer: sym(l) at bits [4l,4l+4)
    __shared__ __align__(16) float Pr [64][4];  // pd + (br - r*pam_a)^2
    __shared__ __align__(16) float Pi2[64][4];  // (bi - r*pam_b)^2
    __shared__ unsigned Hist[128];
    __shared__ unsigned long long EqK[128];
    __shared__ float  WMin[4], WMax[4];
    __shared__ float  PD0[4][32], PD1[4][32];
    __shared__ int S_binfo;
    __shared__ int SelCnt;
    __shared__ int EqCnt;

    // ---------------- load ----------------
    #pragma unroll
    for (int t = tid; t < 256; t += 128)
        Lsh[t >> 4][t & 15] = make_float2(g_sr[b*256 + t], g_si[b*256 + t]);
    Hts[tid >> 3][tid & 7] = make_float2(g_hr[b*128 + tid], g_hi[b*128 + tid]);
    if (tid < 16)  Hts[tid][8] = make_float2(g_yr[b*16 + tid], g_yi[b*16 + tid]);
    if (tid >= 112) { int q = tid - 112; Pts[q] = make_float2(g_pr[q], g_pi[q]); }
    __syncthreads();

    // ---------------- Cholesky 16x16 complex (warp 0) ----------------
    if (wrp == 0) {
        #pragma unroll 1
        for (int jc = 0; jc < 16; jc++) {
            float sx = 0.f, sy = 0.f;
            if (lane >= jc && lane < 16) {
                float2 a0 = Lsh[lane][jc];
                sx = a0.x; sy = a0.y;
                for (int k = 0; k < jc; k++) {       // s -= L[i,k]*conj(L[jc,k])
                    float2 a = Lsh[lane][k], c = Lsh[jc][k];
                    sx -= a.x*c.x + a.y*c.y;
                    sy -= a.y*c.x - a.x*c.y;
                }
            }
            float dj = __shfl_sync(FULLM, sx, jc);
            float dl = sqrtf(dj);
            if (lane == jc) Lsh[lane][jc] = make_float2(dl, 0.f);
            else if (lane > jc && lane < 16) Lsh[lane][jc] = make_float2(sx/dl, sy/dl);
            __syncwarp();
        }
    }
    __syncthreads();

    // ---------------- forward solve L X = [h | y] ----------------
    for (int c = wrp; c < 9; c += 4) {
        #pragma unroll 1
        for (int i = 0; i < 16; i++) {
            float xr = 0.f, xi = 0.f;
            if (lane == i) {
                float2 v = Hts[i][c];
                float dd = Lsh[i][i].x;
                xr = v.x / dd; xi = v.y / dd;
                Hts[i][c] = make_float2(xr, xi);
            }
            xr = __shfl_sync(FULLM, xr, i);
            xi = __shfl_sync(FULLM, xi, i);
            if (lane > i && lane < 16) {
                float2 lij = Lsh[lane][i];
                float2 v = Hts[lane][c];
                v.x -= lij.x*xr - lij.y*xi;
                v.y -= lij.x*xi + lij.y*xr;
                Hts[lane][c] = v;
            }
            __syncwarp();
        }
    }
    __syncthreads();

    // ---------------- Gram G = ht^H ht, z = ht^H yt ----------------
    if (tid < 64) {
        int i = tid >> 3, j = tid & 7;
        float gx = 0.f, gy = 0.f;
        #pragma unroll
        for (int m = 0; m < 16; m++) {
            float2 a = Hts[m][i], c = Hts[m][j];
            gx += a.x*c.x + a.y*c.y;
            gy += a.x*c.y - a.y*c.x;
        }
        Gsh[i][j] = make_float2(gx, gy);
    } else if (tid < 72) {
        int i = tid - 64;
        float gx = 0.f, gy = 0.f;
        #pragma unroll
        for (int m = 0; m < 16; m++) {
            float2 a = Hts[m][i], c = Hts[m][8];
            gx += a.x*c.x + a.y*c.y;
            gy += a.x*c.y - a.y*c.x;
        }
        Zsh[i] = make_float2(gx, gy);
    }
    __syncthreads();

    // ---------------- ordering (stable argsort of -norms) ----------------
    if (tid < 8) {
        float ni = Gsh[tid][tid].x;
        int rank = 0;
        #pragma unroll
        for (int j = 0; j < 8; j++) {
            float nj = Gsh[j][j].x;
            rank += (nj > ni) || (nj == ni && j < tid);
        }
        Order[rank] = tid;
    }
    __syncthreads();
    if (tid < 64) {
        int i = tid >> 3, j = tid & 7;
        Csh[i][j] = Gsh[Order[i]][Order[j]];
    } else if (tid < 72) {
        Ybar[tid - 64] = Zsh[Order[tid - 64]];
    }
    __syncthreads();

    // ------------- Cholesky 8x8 of permuted Gram + solve C ybar = z_p ------
    if (wrp == 0) {
        #pragma unroll 1
        for (int jc = 0; jc < 8; jc++) {
            float sx = 0.f, sy = 0.f;
            if (lane >= jc && lane < 8) {
                float2 a0 = Csh[lane][jc]; sx = a0.x; sy = a0.y;
                for (int k = 0; k < jc; k++) {
                    float2 a = Csh[lane][k], c = Csh[jc][k];
                    sx -= a.x*c.x + a.y*c.y;
                    sy -= a.y*c.x - a.x*c.y;
                }
            }
            float dj = __shfl_sync(FULLM, sx, jc);
            float dl = sqrtf(dj);
            if (lane == jc) Csh[lane][jc] = make_float2(dl, 0.f);
            else if (lane > jc && lane < 8) Csh[lane][jc] = make_float2(sx/dl, sy/dl);
            __syncwarp();
        }
        #pragma unroll 1
        for (int i = 0; i < 8; i++) {
            float xr = 0.f, xi = 0.f;
            if (lane == i) {
                float2 v = Ybar[i];
                float dd = Csh[i][i].x;
                xr = v.x / dd; xi = v.y / dd;
                Ybar[i] = make_float2(xr, xi);
            }
            xr = __shfl_sync(FULLM, xr, i);
            xi = __shfl_sync(FULLM, xi, i);
            if (lane > i && lane < 8) {
                float2 lij = Csh[lane][i];
                float2 v = Ybar[lane];
                v.x -= lij.x*xr - lij.y*xi;
                v.y -= lij.x*xi + lij.y*xr;
                Ybar[lane] = v;
            }
            __syncwarp();
        }
    }
    __syncthreads();

    // ---------------- layer 7: 16 initial candidates ----------------
    int cur = 0;
    if (tid < 16) {
        float r77 = Csh[7][7].x;
        float2 p = Pts[tid];
        float rr = Ybar[7].x - r77*p.x;
        float ri = Ybar[7].y - r77*p.y;
        Cdist[0][tid] = rr*rr + ri*ri;
        Csym[0][tid] = (unsigned)tid << 28;
    }
    __syncthreads();

    // ---------------- layers 6..0 ----------------
    for (int l = 6; l >= 0; l--) {
        const bool full = (l != 6);
        const int nP  = full ? 64 : 16;
        const int cnt = full ? 8  : 2;
        const int nxt = cur ^ 1;

        if (tid == 0) { SelCnt = 0; EqCnt = 0; }

        // per-parent separable distance tables
        if (tid < nP) {
            unsigned sym = Csym[cur][tid];
            float pd = Cdist[cur][tid];
            float ir = 0.f, ii = 0.f;
            for (int j = l + 1; j < 8; j++) {
                int q = (sym >> (4*j)) & 15;
                float2 c = Csh[j][l];
                float2 p = Pts[q];
                ir += c.x*p.x + c.y*p.y;
                ii += c.x*p.y - c.y*p.x;
            }
            float br = Ybar[l].x - ir;
            float bi = Ybar[l].y - ii;
            float rll = Csh[l][l].x;
            float4 prv, piv;
            {
                float t0 = fmaf(-rll, Pts[0].x,  br);
                float t1 = fmaf(-rll, Pts[2].x,  br);
                float t2 = fmaf(-rll, Pts[8].x,  br);
                float t3 = fmaf(-rll, Pts[10].x, br);
                prv.x = fmaf(t0, t0, pd); prv.y = fmaf(t1, t1, pd);
                prv.z = fmaf(t2, t2, pd); prv.w = fmaf(t3, t3, pd);
            }
            {
                float t0 = fmaf(-rll, Pts[0].y, bi);
                float t1 = fmaf(-rll, Pts[1].y, bi);
                float t2 = fmaf(-rll, Pts[4].y, bi);
                float t3 = fmaf(-rll, Pts[5].y, bi);
                piv.x = t0*t0; piv.y = t1*t1; piv.z = t2*t2; piv.w = t3*t3;
            }
            *(float4*)Pr[tid]  = prv;
            *(float4*)Pi2[tid] = piv;
        }
        __syncthreads();

        // children distances (registers only)
        float distr[8];
        unsigned selm = 0u;
        unsigned actm = full ? 0xffu : 0x3u;
        if (full) {
            const int p = tid >> 1;
            const float4 prv = *(const float4*)Pr[p];
            const float4 piv = *(const float4*)Pi2[p];
            const float pa0 = (tid & 1) ? prv.z : prv.x;
            const float pa1 = (tid & 1) ? prv.w : prv.y;
            distr[0] = pa0 + piv.x;  distr[1] = pa0 + piv.y;
            distr[2] = pa1 + piv.x;  distr[3] = pa1 + piv.y;
            distr[4] = pa0 + piv.z;  distr[5] = pa0 + piv.w;
            distr[6] = pa1 + piv.z;  distr[7] = pa1 + piv.w;
        } else {
            #pragma unroll
            for (int j = 0; j < 2; j++) {
                int idx = tid*2 + j;
                int p = idx >> 4, q = idx & 15;
                int a  = ((q >> 2) & 2) | ((q >> 1) & 1);
                int bb = ((q >> 1) & 2) | (q & 1);
                distr[j] = Pr[p][a] + Pi2[p][bb];
            }
        }

        // min/max + hist zero
        float mn = 1e30f, mx = -1e30f;
        #pragma unroll
        for (int j = 0; j < 8; j++) {
            if (j < cnt) { mn = fminf(mn, distr[j]); mx = fmaxf(mx, distr[j]); }
        }
        #pragma unroll
        for (int o = 16; o; o >>= 1) {
            mn = fminf(mn, __shfl_xor_sync(FULLM, mn, o));
            mx = fmaxf(mx, __shfl_xor_sync(FULLM, mx, o));
        }
        if (lane == 0) { WMin[wrp] = mn; WMax[wrp] = mx; }
        Hist[tid] = 0u;
        __syncthreads();

        float lo = fminf(fminf(WMin[0], WMin[1]), fminf(WMin[2], WMin[3]));
        float hi = fmaxf(fmaxf(WMax[0], WMax[1]), fmaxf(WMax[2], WMax[3]));
        int c_sel = 0;

        // adaptive fixed-point select (monotone key; exact ties via EqK)
        #pragma unroll 1
        for (int lev = 0; ; lev++) {
            if (lev) { __syncthreads(); Hist[tid] = 0u; __syncthreads(); }
            float scale = 128.f / fmaxf(hi - lo, 1e-30f);
            int binr[8];
            #pragma unroll
            for (int j = 0; j < 8; j++) {
                if (j < cnt && ((actm >> j) & 1)) {
                    int bn = (int)((distr[j] - lo) * scale);
                    bn = bn > 127 ? 127 : bn;
                    binr[j] = bn;
                    atomicAdd(&Hist[bn], 1u);
                }
            }
            __syncthreads();
            if (wrp == 0) {
                int h0 = (int)Hist[lane*4 + 0];
                int h1 = (int)Hist[lane*4 + 1];
                int h2 = (int)Hist[lane*4 + 2];
                int h3 = (int)Hist[lane*4 + 3];
                int ssum = h0 + h1 + h2 + h3;
                int incl = ssum;
                #pragma unroll
                for (int off = 1; off < 32; off <<= 1) {
                    int v = __shfl_up_sync(FULLM, incl, off);
                    if (lane >= off) incl += v;
                }
                int excl = incl - ssum;
                int target = 63 - c_sel;
                if (excl <= target && target < incl) {
                    int cum = excl, bsel = lane*4;
                    if (target >= cum + h0) { cum += h0; bsel++;
                        if (target >= cum + h1) { cum += h1; bsel++;
                            if (target >= cum + h2) { cum += h2; bsel++; } } }
                    S_binfo = (bsel << 16) | cum;
                }
            }
            __syncthreads();
            int info = S_binfo;
            int cb = info >> 16;
            c_sel += info & 0xffff;
            int mcrit = (int)Hist[cb];
            #pragma unroll
            for (int j = 0; j < 8; j++) {
                if (j < cnt && ((actm >> j) & 1)) {
                    if (binr[j] < cb)      { selm |= 1u << j; actm &= ~(1u << j); }
                    else if (binr[j] > cb) { actm &= ~(1u << j); }
                }
            }
            if (mcrit <= 64 || lev == 3) break;
            float w = (hi - lo) * 0.0078125f;
            float nlo = fmaf((float)cb, w, lo);
            hi = nlo + w;
            lo = nlo;
        }

        // ballot-scan compaction: one atomic per warp per counter
        {
            int nsel = __popc(selm), neq = __popc(actm);
            int packed = nsel | (neq << 16);
            int incl = packed;
            #pragma unroll
            for (int off = 1; off < 32; off <<= 1) {
                int v = __shfl_up_sync(FULLM, incl, off);
                if (lane >= off) incl += v;
            }
            int excl = incl - packed;
            int tot  = __shfl_sync(FULLM, incl, 31);
            int sb = 0, eb = 0;
            if (lane == 0) {
                sb = atomicAdd(&SelCnt, tot & 0xffff);
                eb = atomicAdd(&EqCnt,  tot >> 16);
            }
            sb = __shfl_sync(FULLM, sb, 0) + (excl & 0xffff);
            eb = __shfl_sync(FULLM, eb, 0) + (excl >> 16);

            const unsigned psym_f = full ? Csym[cur][tid >> 1] : 0u;
            #pragma unroll
            for (int j = 0; j < 8; j++) {
                if (j < cnt) {
                    int idx, q; unsigned psym;
                    if (full) {
                        idx = tid*8 + j;
                        q = ((tid & 1) << 3) | j;
                        psym = psym_f;
                    } else {
                        idx = tid*2 + j;
                        q = idx & 15;
                        psym = Csym[cur][idx >> 4];
                    }
                    if ((selm >> j) & 1) {
                        Cdist[nxt][sb] = distr[j];
                        Csym[nxt][sb]  = psym | ((unsigned)q << (4*l));
                        sb++;
                    } else if ((actm >> j) & 1) {
                        if (eb < 128)
                            EqK[eb] = (((unsigned long long)__float_as_uint(distr[j])) << 10)
                                    | (unsigned)idx;
                        eb++;
                    }
                }
            }
        }
        __syncthreads();
        {
            int need = 64 - c_sel;
            int mm = EqCnt < 128 ? EqCnt : 128;
            if (tid < mm) {
                unsigned long long mykey = EqK[tid];
                int rank = 0;
                for (int j = 0; j < mm; j++) rank += (EqK[j] < mykey);
                if (rank < need) {
                    int s = c_sel + rank;
                    int idx = (int)(mykey & 1023ull);
                    int p = idx >> 4, q = idx & 15;
                    Cdist[nxt][s] = __uint_as_float((unsigned)(mykey >> 10));
                    Csym[nxt][s]  = Csym[cur][p] | ((unsigned)q << (4*l));
                }
            }
        }
        __syncthreads();
        cur = nxt;
    }

    // ---------------- LLR (parallel over 4 warps) ----------------
    {
        int l = lane >> 2, j = lane & 3;
        float d0 = 1000000000.0f, d1 = 1000000000.0f;
        #pragma unroll 1
        for (int k = wrp*16; k < wrp*16 + 16; k++) {
            float d = Cdist[cur][k];
            int q = (int)((Csym[cur][k] >> (4*l)) & 15u);
            if ((q >> (3 - j)) & 1) d1 = fminf(d1, d);
            else                    d0 = fminf(d0, d);
        }
        PD0[wrp][lane] = d0;
        PD1[wrp][lane] = d1;
    }
    __syncthreads();
    if (tid < 32) {
        int l = tid >> 2, j = tid & 3;
        float d0 = fminf(fminf(PD0[0][tid], PD0[1][tid]), fminf(PD0[2][tid], PD0[3][tid]));
        float d1 = fminf(fminf(PD1[0][tid], PD1[1][tid]), fminf(PD1[2][tid], PD1[3][tid]));
        float llr = fminf(fmaxf(d0 - d1, -20.f), 20.f);
        g_out[b*32 + Order[l]*4 + j] = llr;
    }
}

extern "C" void kernel_launch(void* const* d_in, const int* in_sizes, int n_in,
                              void* d_out, int out_size)
{
    const float* yr = (const float*)d_in[0];
    const float* yi = (const float*)d_in[1];
    const float* hr = (const float*)d_in[2];
    const float* hi = (const float*)d_in[3];
    const float* sr = (const float*)d_in[4];
    const float* si = (const float*)d_in[5];
    const float* pr = (const float*)d_in[6];
    const float* pi = (const float*)d_in[7];
    int B = in_sizes[0] / 16;
    kbest_kernel<<<B, 128>>>(yr, yi, hr, hi, sr, si, pr, pi, (float*)d_out);
}

// round 6
// speedup vs baseline: 1.4944x; 1.0340x over previous
#include <cuda_runtime.h>

// KBestDetector: B=16384, M=16 rx, S=8 streams, 16-QAM (NBPS=4), K=64.
// One CTA (128 threads) per batch, 8 children/thread in the K-best loop.
//
//  1) chol(S) 16x16 complex (warp 0)
//  2) forward-solve L\[h|y]  (warp per rhs column, round-robin)
//  3) G = ht^H ht, z = ht^H yt
//  4) order by diag(G) desc; permute; chol 8x8 -> R=C^H; ybar = C^{-1} z_p
//  5) K-best layers: separable (4x4 PAM) child distances in registers;
//     certified pruning bound T = max_p(best child of p) — valid ONLY when
//     #parents == K (full layers); layer 6 (16 parents) uses T = global max
//     (no pruning). Exact top-64 via adaptive 128-bin fixed-point select +
//     exact tie cleanup; ballot-scan compaction.
//  6) LLR mins over final 64 candidates, parallel over 4 warps

#define FULLM 0xffffffffu

__global__ void __launch_bounds__(128, 10) kbest_kernel(
    const float* __restrict__ g_yr, const float* __restrict__ g_yi,
    const float* __restrict__ g_hr, const float* __restrict__ g_hi,
    const float* __restrict__ g_sr, const float* __restrict__ g_si,
    const float* __restrict__ g_pr, const float* __restrict__ g_pi,
    float* __restrict__ g_out)
{
    const int b    = blockIdx.x;
    const int tid  = threadIdx.x;
    const int lane = tid & 31;
    const int wrp  = tid >> 5;

    __shared__ float2 Lsh[16][17];     // S -> its Cholesky L
    __shared__ float2 Hts[16][9];      // whitened h (cols 0..7) and y (col 8)
    __shared__ float2 Gsh[8][8];
    __shared__ float2 Csh[8][8];       // permuted Gram -> Cholesky (R = C^H)
    __shared__ float2 Zsh[8];
    __shared__ float2 Ybar[8];
    __shared__ int    Order[8];
    __shared__ float2 Pts[16];
    __shared__ float    Cdist[2][64];
    __shared__ unsigned Csym[2][64];   // 4 bits/layer: sym(l) at bits [4l,4l+4)
    __shared__ __align__(16) float Pr [64][4];  // pd + (br - r*pam_a)^2
    __shared__ __align__(16) float Pi2[64][4];  // (bi - r*pam_b)^2
    __shared__ unsigned Hist[128];
    __shared__ unsigned long long EqK[128];
    __shared__ float  WMin[4], WMax[4];
    __shared__ float  PD0[4][32], PD1[4][32];
    __shared__ int S_binfo;
    __shared__ int SelCnt;
    __shared__ int EqCnt;

    // ---------------- load ----------------
    #pragma unroll
    for (int t = tid; t < 256; t += 128)
        Lsh[t >> 4][t & 15] = make_float2(g_sr[b*256 + t], g_si[b*256 + t]);
    Hts[tid >> 3][tid & 7] = make_float2(g_hr[b*128 + tid], g_hi[b*128 + tid]);
    if (tid < 16)  Hts[tid][8] = make_float2(g_yr[b*16 + tid], g_yi[b*16 + tid]);
    if (tid >= 112) { int q = tid - 112; Pts[q] = make_float2(g_pr[q], g_pi[q]); }
    __syncthreads();

    // ---------------- Cholesky 16x16 complex (warp 0) ----------------
    if (wrp == 0) {
        #pragma unroll 1
        for (int jc = 0; jc < 16; jc++) {
            float sx = 0.f, sy = 0.f;
            if (lane >= jc && lane < 16) {
                float2 a0 = Lsh[lane][jc];
                sx = a0.x; sy = a0.y;
                for (int k = 0; k < jc; k++) {       // s -= L[i,k]*conj(L[jc,k])
                    float2 a = Lsh[lane][k], c = Lsh[jc][k];
                    sx -= a.x*c.x + a.y*c.y;
                    sy -= a.y*c.x - a.x*c.y;
                }
            }
            float dj = __shfl_sync(FULLM, sx, jc);
            float dl = sqrtf(dj);
            if (lane == jc) Lsh[lane][jc] = make_float2(dl, 0.f);
            else if (lane > jc && lane < 16) Lsh[lane][jc] = make_float2(sx/dl, sy/dl);
            __syncwarp();
        }
    }
    __syncthreads();

    // ---------------- forward solve L X = [h | y] ----------------
    for (int c = wrp; c < 9; c += 4) {
        #pragma unroll 1
        for (int i = 0; i < 16; i++) {
            float xr = 0.f, xi = 0.f;
            if (lane == i) {
                float2 v = Hts[i][c];
                float dd = Lsh[i][i].x;
                xr = v.x / dd; xi = v.y / dd;
                Hts[i][c] = make_float2(xr, xi);
            }
            xr = __shfl_sync(FULLM, xr, i);
            xi = __shfl_sync(FULLM, xi, i);
            if (lane > i && lane < 16) {
                float2 lij = Lsh[lane][i];
                float2 v = Hts[lane][c];
                v.x -= lij.x*xr - lij.y*xi;
                v.y -= lij.x*xi + lij.y*xr;
                Hts[lane][c] = v;
            }
            __syncwarp();
        }
    }
    __syncthreads();

    // ---------------- Gram G = ht^H ht, z = ht^H yt ----------------
    if (tid < 64) {
        int i = tid >> 3, j = tid & 7;
        float gx = 0.f, gy = 0.f;
        #pragma unroll
        for (int m = 0; m < 16; m++) {
            float2 a = Hts[m][i], c = Hts[m][j];
            gx += a.x*c.x + a.y*c.y;
            gy += a.x*c.y - a.y*c.x;
        }
        Gsh[i][j] = make_float2(gx, gy);
    } else if (tid < 72) {
        int i = tid - 64;
        float gx = 0.f, gy = 0.f;
        #pragma unroll
        for (int m = 0; m < 16; m++) {
            float2 a = Hts[m][i], c = Hts[m][8];
            gx += a.x*c.x + a.y*c.y;
            gy += a.x*c.y - a.y*c.x;
        }
        Zsh[i] = make_float2(gx, gy);
    }
    __syncthreads();

    // ---------------- ordering (stable argsort of -norms) ----------------
    if (tid < 8) {
        float ni = Gsh[tid][tid].x;
        int rank = 0;
        #pragma unroll
        for (int j = 0; j < 8; j++) {
            float nj = Gsh[j][j].x;
            rank += (nj > ni) || (nj == ni && j < tid);
        }
        Order[rank] = tid;
    }
    __syncthreads();
    if (tid < 64) {
        int i = tid >> 3, j = tid & 7;
        Csh[i][j] = Gsh[Order[i]][Order[j]];
    } else if (tid < 72) {
        Ybar[tid - 64] = Zsh[Order[tid - 64]];
    }
    __syncthreads();

    // ------------- Cholesky 8x8 of permuted Gram + solve C ybar = z_p ------
    if (wrp == 0) {
        #pragma unroll 1
        for (int jc = 0; jc < 8; jc++) {
            float sx = 0.f, sy = 0.f;
            if (lane >= jc && lane < 8) {
                float2 a0 = Csh[lane][jc]; sx = a0.x; sy = a0.y;
                for (int k = 0; k < jc; k++) {
                    float2 a = Csh[lane][k], c = Csh[jc][k];
                    sx -= a.x*c.x + a.y*c.y;
                    sy -= a.y*c.x - a.x*c.y;
                }
            }
            float dj = __shfl_sync(FULLM, sx, jc);
            float dl = sqrtf(dj);
            if (lane == jc) Csh[lane][jc] = make_float2(dl, 0.f);
            else if (lane > jc && lane < 8) Csh[lane][jc] = make_float2(sx/dl, sy/dl);
            __syncwarp();
        }
        #pragma unroll 1
        for (int i = 0; i < 8; i++) {
            float xr = 0.f, xi = 0.f;
            if (lane == i) {
                float2 v = Ybar[i];
                float dd = Csh[i][i].x;
                xr = v.x / dd; xi = v.y / dd;
                Ybar[i] = make_float2(xr, xi);
            }
            xr = __shfl_sync(FULLM, xr, i);
            xi = __shfl_sync(FULLM, xi, i);
            if (lane > i && lane < 8) {
                float2 lij = Csh[lane][i];
                float2 v = Ybar[lane];
                v.x -= lij.x*xr - lij.y*xi;
                v.y -= lij.x*xi + lij.y*xr;
                Ybar[lane] = v;
            }
            __syncwarp();
        }
    }
    __syncthreads();

    // ---------------- layer 7: 16 initial candidates ----------------
    int cur = 0;
    if (tid < 16) {
        float r77 = Csh[7][7].x;
        float2 p = Pts[tid];
        float rr = Ybar[7].x - r77*p.x;
        float ri = Ybar[7].y - r77*p.y;
        Cdist[0][tid] = rr*rr + ri*ri;
        Csym[0][tid] = (unsigned)tid << 28;
    }
    __syncthreads();

    // ---------------- layers 6..0 ----------------
    for (int l = 6; l >= 0; l--) {
        const bool full = (l != 6);
        const int nP  = full ? 64 : 16;
        const int cnt = full ? 8  : 2;
        const int nxt = cur ^ 1;

        if (tid == 0) { SelCnt = 0; EqCnt = 0; S_binfo = 127 << 16; }

        // per-parent separable distance tables
        if (tid < nP) {
            unsigned sym = Csym[cur][tid];
            float pd = Cdist[cur][tid];
            float ir = 0.f, ii = 0.f;
            for (int j = l + 1; j < 8; j++) {
                int q = (sym >> (4*j)) & 15;
                float2 c = Csh[j][l];
                float2 p = Pts[q];
                ir += c.x*p.x + c.y*p.y;
                ii += c.x*p.y - c.y*p.x;
            }
            float br = Ybar[l].x - ir;
            float bi = Ybar[l].y - ii;
            float rll = Csh[l][l].x;
            float4 prv, piv;
            {
                float t0 = fmaf(-rll, Pts[0].x,  br);
                float t1 = fmaf(-rll, Pts[2].x,  br);
                float t2 = fmaf(-rll, Pts[8].x,  br);
                float t3 = fmaf(-rll, Pts[10].x, br);
                prv.x = fmaf(t0, t0, pd); prv.y = fmaf(t1, t1, pd);
                prv.z = fmaf(t2, t2, pd); prv.w = fmaf(t3, t3, pd);
            }
            {
                float t0 = fmaf(-rll, Pts[0].y, bi);
                float t1 = fmaf(-rll, Pts[1].y, bi);
                float t2 = fmaf(-rll, Pts[4].y, bi);
                float t3 = fmaf(-rll, Pts[5].y, bi);
                piv.x = t0*t0; piv.y = t1*t1; piv.z = t2*t2; piv.w = t3*t3;
            }
            *(float4*)Pr[tid]  = prv;
            *(float4*)Pi2[tid] = piv;
        }
        __syncthreads();

        // children distances (registers only)
        float distr[8];
        unsigned selm = 0u;
        if (full) {
            const int p = tid >> 1;
            const float4 prv = *(const float4*)Pr[p];
            const float4 piv = *(const float4*)Pi2[p];
            const float pa0 = (tid & 1) ? prv.z : prv.x;
            const float pa1 = (tid & 1) ? prv.w : prv.y;
            distr[0] = pa0 + piv.x;  distr[1] = pa0 + piv.y;
            distr[2] = pa1 + piv.x;  distr[3] = pa1 + piv.y;
            distr[4] = pa0 + piv.z;  distr[5] = pa0 + piv.w;
            distr[6] = pa1 + piv.z;  distr[7] = pa1 + piv.w;
        } else {
            #pragma unroll
            for (int j = 0; j < 2; j++) {
                int idx = tid*2 + j;
                int p = idx >> 4, q = idx & 15;
                int a  = ((q >> 2) & 2) | ((q >> 1) & 1);
                int bb = ((q >> 1) & 2) | (q & 1);
                distr[j] = Pr[p][a] + Pi2[p][bb];
            }
        }

        // per-thread min; certified bound payload:
        //  full layers (64 parents): parent-best min -> T = max_p pb_p bounds d_(64)
        //  layer 6 (16 parents):     bound invalid for K=64 -> use per-thread MAX
        //                            so T = global max (pruning disabled)
        float mn8 = 1e30f;
        #pragma unroll
        for (int j = 0; j < 8; j++)
            if (j < cnt) mn8 = fminf(mn8, distr[j]);
        float pb;
        if (full) {
            pb = fminf(mn8, __shfl_xor_sync(FULLM, mn8, 1));   // parent = 2 threads
        } else {
            pb = fmaxf(distr[0], distr[1]);                    // thread max
        }
        float mnW = mn8, tW = pb;
        #pragma unroll
        for (int o = 16; o; o >>= 1) {
            mnW = fminf(mnW, __shfl_xor_sync(FULLM, mnW, o));
            tW  = fmaxf(tW,  __shfl_xor_sync(FULLM, tW,  o));
        }
        if (lane == 0) { WMin[wrp] = mnW; WMax[wrp] = tW; }
        Hist[tid] = 0u;
        __syncthreads();

        float lo = fminf(fminf(WMin[0], WMin[1]), fminf(WMin[2], WMin[3]));
        float T  = fmaxf(fmaxf(WMax[0], WMax[1]), fmaxf(WMax[2], WMax[3]));
        float hi = T;
        int c_sel = 0;

        // prune: d > T can never be in the exact top-64
        unsigned actm = 0u;
        #pragma unroll
        for (int j = 0; j < 8; j++)
            if (j < cnt && distr[j] <= T) actm |= 1u << j;

        // adaptive fixed-point select (monotone key; exact ties via EqK)
        #pragma unroll 1
        for (int lev = 0; ; lev++) {
            if (lev) { __syncthreads(); Hist[tid] = 0u; __syncthreads(); }
            float scale = 128.f / fmaxf(hi - lo, 1e-30f);
            int binr[8];
            #pragma unroll
            for (int j = 0; j < 8; j++) {
                if (j < cnt && ((actm >> j) & 1)) {
                    int bn = (int)((distr[j] - lo) * scale);
                    bn = bn < 0 ? 0 : (bn > 127 ? 127 : bn);
                    binr[j] = bn;
                    atomicAdd(&Hist[bn], 1u);
                }
            }
            __syncthreads();
            if (wrp == 0) {
                int h0 = (int)Hist[lane*4 + 0];
                int h1 = (int)Hist[lane*4 + 1];
                int h2 = (int)Hist[lane*4 + 2];
                int h3 = (int)Hist[lane*4 + 3];
                int ssum = h0 + h1 + h2 + h3;
                int incl = ssum;
                #pragma unroll
                for (int off = 1; off < 32; off <<= 1) {
                    int v = __shfl_up_sync(FULLM, incl, off);
                    if (lane >= off) incl += v;
                }
                int excl = incl - ssum;
                int target = 63 - c_sel;
                if (excl <= target && target < incl) {
                    int cum = excl, bsel = lane*4;
                    if (target >= cum + h0) { cum += h0; bsel++;
                        if (target >= cum + h1) { cum += h1; bsel++;
                            if (target >= cum + h2) { cum += h2; bsel++; } } }
                    S_binfo = (bsel << 16) | cum;
                }
            }
            __syncthreads();
            int info = S_binfo;
            int cb = info >> 16;
            c_sel += info & 0xffff;
            int mcrit = (int)Hist[cb];
            #pragma unroll
            for (int j = 0; j < 8; j++) {
                if (j < cnt && ((actm >> j) & 1)) {
                    if (binr[j] < cb)      { selm |= 1u << j; actm &= ~(1u << j); }
                    else if (binr[j] > cb) { actm &= ~(1u << j); }
                }
            }
            if (mcrit <= 64 || lev == 3) break;
            float w = (hi - lo) * 0.0078125f;
            float nlo = fmaf((float)cb, w, lo);
            hi = nlo + w;
            lo = nlo;
        }

        // ballot-scan compaction: one atomic per warp per counter
        {
            int nsel = __popc(selm), neq = __popc(actm);
            int packed = nsel | (neq << 16);
            int incl = packed;
            #pragma unroll
            for (int off = 1; off < 32; off <<= 1) {
                int v = __shfl_up_sync(FULLM, incl, off);
                if (lane >= off) incl += v;
            }
            int excl = incl - packed;
            int tot  = __shfl_sync(FULLM, incl, 31);
            int sb = 0, eb = 0;
            if (lane == 0) {
                sb = atomicAdd(&SelCnt, tot & 0xffff);
                eb = atomicAdd(&EqCnt,  tot >> 16);
            }
            sb = __shfl_sync(FULLM, sb, 0) + (excl & 0xffff);
            eb = __shfl_sync(FULLM, eb, 0) + (excl >> 16);

            const unsigned psym_f = full ? Csym[cur][tid >> 1] : 0u;
            #pragma unroll
            for (int j = 0; j < 8; j++) {
                if (j < cnt) {
                    int idx, q; unsigned psym;
                    if (full) {
                        idx = tid*8 + j;
                        q = ((tid & 1) << 3) | j;
                        psym = psym_f;
                    } else {
                        idx = tid*2 + j;
                        q = idx & 15;
                        psym = Csym[cur][idx >> 4];
                    }
                    if ((selm >> j) & 1) {
                        if (sb < 64) {
                            Cdist[nxt][sb] = distr[j];
                            Csym[nxt][sb]  = psym | ((unsigned)q << (4*l));
                        }
                        sb++;
                    } else if ((actm >> j) & 1) {
                        if (eb < 128)
                            EqK[eb] = (((unsigned long long)__float_as_uint(distr[j])) << 10)
                                    | (unsigned)idx;
                        eb++;
                    }
                }
            }
        }
        __syncthreads();
        {
            int need = 64 - c_sel;
            int mm = EqCnt < 128 ? EqCnt : 128;
            if (tid < mm) {
                unsigned long long mykey = EqK[tid];
                int rank = 0;
                for (int j = 0; j < mm; j++) rank += (EqK[j] < mykey);
                if (rank < need) {
                    int s = c_sel + rank;
                    if (s < 64) {
                        int idx = (int)(mykey & 1023ull);
                        int p = idx >> 4, q = idx & 15;
                        Cdist[nxt][s] = __uint_as_float((unsigned)(mykey >> 10));
                        Csym[nxt][s]  = Csym[cur][p] | ((unsigned)q << (4*l));
                    }
                }
            }
        }
        __syncthreads();
        cur = nxt;
    }

    // ---------------- LLR (parallel over 4 warps) ----------------
    {
        int l = lane >> 2, j = lane & 3;
        float d0 = 1000000000.0f, d1 = 1000000000.0f;
        #pragma unroll 1
        for (int k = wrp*16; k < wrp*16 + 16; k++) {
            float d = Cdist[cur][k];
            int q = (int)((Csym[cur][k] >> (4*l)) & 15u);
            if ((q >> (3 - j)) & 1) d1 = fminf(d1, d);
            else                    d0 = fminf(d0, d);
        }
        PD0[wrp][lane] = d0;
        PD1[wrp][lane] = d1;
    }
    __syncthreads();
    if (tid < 32) {
        int l = tid >> 2, j = tid & 3;
        float d0 = fminf(fminf(PD0[0][tid], PD0[1][tid]), fminf(PD0[2][tid], PD0[3][tid]));
        float d1 = fminf(fminf(PD1[0][tid], PD1[1][tid]), fminf(PD1[2][tid], PD1[3][tid]));
        float llr = fminf(fmaxf(d0 - d1, -20.f), 20.f);
        g_out[b*32 + Order[l]*4 + j] = llr;
    }
}

extern "C" void kernel_launch(void* const* d_in, const int* in_sizes, int n_in,
                              void* d_out, int out_size)
{
    const float* yr = (const float*)d_in[0];
    const float* yi = (const float*)d_in[1];
    const float* hr = (const float*)d_in[2];
    const float* hi = (const float*)d_in[3];
    const float* sr = (const float*)d_in[4];
    const float* si = (const float*)d_in[5];
    const float* pr = (const float*)d_in[6];
    const float* pi = (const float*)d_in[7];
    int B = in_sizes[0] / 16;
    kbest_kernel<<<B, 128>>>(yr, yi, hr, hi, sr, si, pr, pi, (float*)d_out);
}

// round 8
// speedup vs baseline: 2.2824x; 1.5274x over previous
#include <cuda_runtime.h>

// KBestDetector: B=16384, M=16 rx, S=8 streams, 16-QAM (NBPS=4), K=64.
// WARP-PER-BATCH: one warp owns one batch end-to-end. CTA = 4 warps = 4
// batches. No __syncthreads anywhere; warp-synchronous throughout.
//
//  1) chol(S) 16x16 complex (lanes 0-15)
//  2) forward-solve L\[h|y], two columns at a time via width-16 shuffles
//  3) G = ht^H ht, z = ht^H yt (72 dot products over lanes)
//  4) order by diag(G) desc; permute; chol 8x8 -> R=C^H; ybar = C^{-1} z_p
//  5) K-best layers: separable (4x4 PAM) distances; 32 children/lane with
//     32-bit active/selected masks; certified bound T = max_p(best child)
//     (full layers only); exact top-64 via adaptive 128-bin select with
//     warp-ballot bin broadcast + exact tie cleanup; scan-based compaction
//     with zero atomics.
//  6) LLR mins over final 64 candidates (one (layer,bit) pair per lane)

#define FULLM 0xffffffffu
#define WPB 4

__global__ void __launch_bounds__(128, 6) kbest_kernel(
    const float* __restrict__ g_yr, const float* __restrict__ g_yi,
    const float* __restrict__ g_hr, const float* __restrict__ g_hi,
    const float* __restrict__ g_sr, const float* __restrict__ g_si,
    const float* __restrict__ g_pr, const float* __restrict__ g_pi,
    float* __restrict__ g_out)
{
    const int lane = threadIdx.x & 31;
    const int wrp  = threadIdx.x >> 5;
    const int b    = blockIdx.x * WPB + wrp;

    __shared__ float2 Lsh[WPB][16][17];
    __shared__ float2 Hts[WPB][16][9];
    __shared__ float2 Gsh[WPB][8][8];
    __shared__ float2 Csh[WPB][8][8];
    __shared__ float2 Zsh[WPB][8];
    __shared__ float2 Ybar[WPB][8];
    __shared__ int    Order[WPB][8];
    __shared__ float2 Pts[WPB][16];
    __shared__ float    Cdist[WPB][2][64];
    __shared__ unsigned Csym[WPB][2][64];
    __shared__ __align__(16) float Prs[WPB][64][4];
    __shared__ __align__(16) float Pis[WPB][64][4];
    __shared__ __align__(16) unsigned Hist[WPB][128];
    __shared__ unsigned long long EqK[WPB][128];

    float2 (*LshW)[17] = Lsh[wrp];
    float2 (*HtsW)[9]  = Hts[wrp];
    float2 (*GshW)[8]  = Gsh[wrp];
    float2 (*CshW)[8]  = Csh[wrp];
    float2 *ZshW  = Zsh[wrp];
    float2 *YbarW = Ybar[wrp];
    int    *OrderW = Order[wrp];
    float2 *PtsW  = Pts[wrp];
    float    (*CdistW)[64] = Cdist[wrp];
    unsigned (*CsymW)[64]  = Csym[wrp];
    float (*PrsW)[4] = Prs[wrp];
    float (*PisW)[4] = Pis[wrp];
    unsigned *HistW = Hist[wrp];
    unsigned long long *EqKW = EqK[wrp];

    // ---------------- load ----------------
    for (int t = lane; t < 256; t += 32)
        LshW[t >> 4][t & 15] = make_float2(g_sr[b*256 + t], g_si[b*256 + t]);
    for (int t = lane; t < 128; t += 32)
        HtsW[t >> 3][t & 7] = make_float2(g_hr[b*128 + t], g_hi[b*128 + t]);
    if (lane < 16) {
        HtsW[lane][8] = make_float2(g_yr[b*16 + lane], g_yi[b*16 + lane]);
        PtsW[lane]    = make_float2(g_pr[lane], g_pi[lane]);
    }
    __syncwarp();

    // ---------------- Cholesky 16x16 complex (lanes 0-15) ----------------
    #pragma unroll 1
    for (int jc = 0; jc < 16; jc++) {
        float sx = 0.f, sy = 0.f;
        if (lane >= jc && lane < 16) {
            float2 a0 = LshW[lane][jc];
            sx = a0.x; sy = a0.y;
            for (int k = 0; k < jc; k++) {       // s -= L[i,k]*conj(L[jc,k])
                float2 a = LshW[lane][k], c = LshW[jc][k];
                sx -= a.x*c.x + a.y*c.y;
                sy -= a.y*c.x - a.x*c.y;
            }
        }
        float dj = __shfl_sync(FULLM, sx, jc);
        float dl = sqrtf(dj);
        if (lane == jc) LshW[lane][jc] = make_float2(dl, 0.f);
        else if (lane > jc && lane < 16) LshW[lane][jc] = make_float2(sx/dl, sy/dl);
        __syncwarp();
    }

    // ------- forward solve L X = [h | y]: two columns per pass -------
    #pragma unroll 1
    for (int cp = 0; cp < 5; cp++) {
        int c = cp*2 + (lane >> 4);
        bool valid = (c < 9);
        int r = lane & 15;
        #pragma unroll 1
        for (int i = 0; i < 16; i++) {
            float xr = 0.f, xi = 0.f;
            if (r == i && valid) {
                float2 v = HtsW[i][c];
                float dd = LshW[i][i].x;
                xr = v.x / dd; xi = v.y / dd;
                HtsW[i][c] = make_float2(xr, xi);
            }
            xr = __shfl_sync(FULLM, xr, i, 16);
            xi = __shfl_sync(FULLM, xi, i, 16);
            if (r > i && valid) {
                float2 lij = LshW[r][i];
                float2 v = HtsW[r][c];
                v.x -= lij.x*xr - lij.y*xi;
                v.y -= lij.x*xi + lij.y*xr;
                HtsW[r][c] = v;
            }
            __syncwarp();
        }
    }

    // ---------------- Gram G = ht^H ht, z = ht^H yt ----------------
    for (int t = lane; t < 72; t += 32) {
        int i = (t < 64) ? (t >> 3) : (t - 64);
        int j = (t < 64) ? (t & 7)  : 8;
        float gx = 0.f, gy = 0.f;
        #pragma unroll
        for (int m = 0; m < 16; m++) {
            float2 a = HtsW[m][i], c = HtsW[m][j];
            gx += a.x*c.x + a.y*c.y;
            gy += a.x*c.y - a.y*c.x;
        }
        if (t < 64) GshW[i][j] = make_float2(gx, gy);
        else        ZshW[i]    = make_float2(gx, gy);
    }
    __syncwarp();

    // ---------------- ordering (stable argsort of -norms) ----------------
    if (lane < 8) {
        float ni = GshW[lane][lane].x;
        int rank = 0;
        #pragma unroll
        for (int j = 0; j < 8; j++) {
            float nj = GshW[j][j].x;
            rank += (nj > ni) || (nj == ni && j < lane);
        }
        OrderW[rank] = lane;
    }
    __syncwarp();
    for (int t = lane; t < 64; t += 32)
        CshW[t >> 3][t & 7] = GshW[OrderW[t >> 3]][OrderW[t & 7]];
    if (lane < 8) YbarW[lane] = ZshW[OrderW[lane]];
    __syncwarp();

    // ------- Cholesky 8x8 of permuted Gram + solve C ybar = z_p -------
    #pragma unroll 1
    for (int jc = 0; jc < 8; jc++) {
        float sx = 0.f, sy = 0.f;
        if (lane >= jc && lane < 8) {
            float2 a0 = CshW[lane][jc]; sx = a0.x; sy = a0.y;
            for (int k = 0; k < jc; k++) {
                float2 a = CshW[lane][k], c = CshW[jc][k];
                sx -= a.x*c.x + a.y*c.y;
                sy -= a.y*c.x - a.x*c.y;
            }
        }
        float dj = __shfl_sync(FULLM, sx, jc);
        float dl = sqrtf(dj);
        if (lane == jc) CshW[lane][jc] = make_float2(dl, 0.f);
        else if (lane > jc && lane < 8) CshW[lane][jc] = make_float2(sx/dl, sy/dl);
        __syncwarp();
    }
    #pragma unroll 1
    for (int i = 0; i < 8; i++) {
        float xr = 0.f, xi = 0.f;
        if (lane == i) {
            float2 v = YbarW[i];
            float dd = CshW[i][i].x;
            xr = v.x / dd; xi = v.y / dd;
            YbarW[i] = make_float2(xr, xi);
        }
        xr = __shfl_sync(FULLM, xr, i);
        xi = __shfl_sync(FULLM, xi, i);
        if (lane > i && lane < 8) {
            float2 lij = CshW[lane][i];
            float2 v = YbarW[lane];
            v.x -= lij.x*xr - lij.y*xi;
            v.y -= lij.x*xi + lij.y*xr;
            YbarW[lane] = v;
        }
        __syncwarp();
    }

    // ---------------- layer 7: 16 initial candidates ----------------
    int cur = 0;
    if (lane < 16) {
        float r77 = CshW[7][7].x;
        float2 p = PtsW[lane];
        float rr = YbarW[7].x - r77*p.x;
        float ri = YbarW[7].y - r77*p.y;
        CdistW[0][lane] = rr*rr + ri*ri;
        CsymW[0][lane]  = (unsigned)lane << 28;
    }
    __syncwarp();

    // ---------------- layers 6..0 ----------------
    for (int l = 6; l >= 0; l--) {
        const bool full = (l != 6);
        const int nP  = full ? 64 : 16;
        const int nxt = cur ^ 1;

        // per-parent separable distance tables
        for (int p = lane; p < nP; p += 32) {
            unsigned sym = CsymW[cur][p];
            float pd = CdistW[cur][p];
            float ir = 0.f, ii = 0.f;
            for (int j = l + 1; j < 8; j++) {
                int q = (sym >> (4*j)) & 15;
                float2 c = CshW[j][l];
                float2 pt = PtsW[q];
                ir += c.x*pt.x + c.y*pt.y;
                ii += c.x*pt.y - c.y*pt.x;
            }
            float br = YbarW[l].x - ir;
            float bi = YbarW[l].y - ii;
            float rll = CshW[l][l].x;
            float4 prv, piv;
            {
                float t0 = fmaf(-rll, PtsW[0].x,  br);
                float t1 = fmaf(-rll, PtsW[2].x,  br);
                float t2 = fmaf(-rll, PtsW[8].x,  br);
                float t3 = fmaf(-rll, PtsW[10].x, br);
                prv.x = fmaf(t0, t0, pd); prv.y = fmaf(t1, t1, pd);
                prv.z = fmaf(t2, t2, pd); prv.w = fmaf(t3, t3, pd);
            }
            {
                float t0 = fmaf(-rll, PtsW[0].y, bi);
                float t1 = fmaf(-rll, PtsW[1].y, bi);
                float t2 = fmaf(-rll, PtsW[4].y, bi);
                float t3 = fmaf(-rll, PtsW[5].y, bi);
                piv.x = t0*t0; piv.y = t1*t1; piv.z = t2*t2; piv.w = t3*t3;
            }
            *(float4*)PrsW[p] = prv;
            *(float4*)PisW[p] = piv;
        }
        *(uint4*)&HistW[lane*4] = make_uint4(0u, 0u, 0u, 0u);
        __syncwarp();

        // pass 1: per-lane min + certificate payload
        float mn, Tpay;
        float4 A0, B0, A1, B1;
        if (full) {
            A0 = *(const float4*)PrsW[2*lane];     B0 = *(const float4*)PisW[2*lane];
            A1 = *(const float4*)PrsW[2*lane + 1]; B1 = *(const float4*)PisW[2*lane + 1];
            #define MIN4_(pa, B) fminf(fminf(pa + B.x, pa + B.y), fminf(pa + B.z, pa + B.w))
            float m0 = fminf(fminf(MIN4_(A0.x, B0), MIN4_(A0.y, B0)),
                             fminf(MIN4_(A0.z, B0), MIN4_(A0.w, B0)));
            float m1 = fminf(fminf(MIN4_(A1.x, B1), MIN4_(A1.y, B1)),
                             fminf(MIN4_(A1.z, B1), MIN4_(A1.w, B1)));
            mn   = fminf(m0, m1);
            Tpay = fmaxf(m0, m1);          // parent-best: certifies d_(64)
        } else {
            A0 = *(const float4*)PrsW[lane >> 1];
            B0 = *(const float4*)PisW[lane >> 1];
            float pa0 = (lane & 1) ? A0.z : A0.x;
            float pa1 = (lane & 1) ? A0.w : A0.y;
            float d0 = pa0 + B0.x, d1 = pa0 + B0.y, d2 = pa1 + B0.x, d3 = pa1 + B0.y;
            float d4 = pa0 + B0.z, d5 = pa0 + B0.w, d6 = pa1 + B0.z, d7 = pa1 + B0.w;
            mn   = fminf(fminf(fminf(d0,d1),fminf(d2,d3)), fminf(fminf(d4,d5),fminf(d6,d7)));
            Tpay = fmaxf(fmaxf(fmaxf(d0,d1),fmaxf(d2,d3)), fmaxf(fmaxf(d4,d5),fmaxf(d6,d7)));
        }
        float lo = mn, T = Tpay;
        #pragma unroll
        for (int o = 16; o; o >>= 1) {
            lo = fminf(lo, __shfl_xor_sync(FULLM, lo, o));
            T  = fmaxf(T,  __shfl_xor_sync(FULLM, T,  o));
        }
        float hi = T;
        float scale = 128.f / fmaxf(hi - lo, 1e-30f);

        // pass 2: prune (d<=T) + level-0 histogram + active mask
        unsigned actm = 0u, selm = 0u;
        #define P2_(k, pa, pb) { float d = (pa) + (pb); \
            if (d <= T) { int bn = (int)((d - lo) * scale); \
                bn = bn < 0 ? 0 : (bn > 127 ? 127 : bn); \
                atomicAdd(&HistW[bn], 1u); actm |= (1u << (k)); } }
        if (full) {
            P2_( 0, A0.x, B0.x) P2_( 1, A0.x, B0.y) P2_( 2, A0.y, B0.x) P2_( 3, A0.y, B0.y)
            P2_( 4, A0.x, B0.z) P2_( 5, A0.x, B0.w) P2_( 6, A0.y, B0.z) P2_( 7, A0.y, B0.w)
            P2_( 8, A0.z, B0.x) P2_( 9, A0.z, B0.y) P2_(10, A0.w, B0.x) P2_(11, A0.w, B0.y)
            P2_(12, A0.z, B0.z) P2_(13, A0.z, B0.w) P2_(14, A0.w, B0.z) P2_(15, A0.w, B0.w)
            P2_(16, A1.x, B1.x) P2_(17, A1.x, B1.y) P2_(18, A1.y, B1.x) P2_(19, A1.y, B1.y)
            P2_(20, A1.x, B1.z) P2_(21, A1.x, B1.w) P2_(22, A1.y, B1.z) P2_(23, A1.y, B1.w)
            P2_(24, A1.z, B1.x) P2_(25, A1.z, B1.y) P2_(26, A1.w, B1.x) P2_(27, A1.w, B1.y)
            P2_(28, A1.z, B1.z) P2_(29, A1.z, B1.w) P2_(30, A1.w, B1.z) P2_(31, A1.w, B1.w)
        } else {
            float pa0 = (lane & 1) ? A0.z : A0.x;
            float pa1 = (lane & 1) ? A0.w : A0.y;
            P2_(0, pa0, B0.x) P2_(1, pa0, B0.y) P2_(2, pa1, B0.x) P2_(3, pa1, B0.y)
            P2_(4, pa0, B0.z) P2_(5, pa0, B0.w) P2_(6, pa1, B0.z) P2_(7, pa1, B0.w)
        }

        // adaptive select loop (exact; ties via EqK)
        int c_sel = 0;
        #pragma unroll 1
        for (int lev = 0; ; lev++) {
            if (lev) {
                __syncwarp();
                *(uint4*)&HistW[lane*4] = make_uint4(0u, 0u, 0u, 0u);
                __syncwarp();
                scale = 128.f / fmaxf(hi - lo, 1e-30f);
                unsigned m = actm;
                while (m) {
                    int k = __ffs(m) - 1; m &= m - 1;
                    int p, q;
                    if (full) { p = (lane << 1) + (k >> 4); q = k & 15; }
                    else      { p = lane >> 1; q = ((lane & 1) << 3) | k; }
                    int a  = ((q >> 2) & 2) | ((q >> 1) & 1);
                    int bq = ((q >> 1) & 2) | (q & 1);
                    float d = PrsW[p][a] + PisW[p][bq];
                    int bn = (int)((d - lo) * scale);
                    bn = bn < 0 ? 0 : (bn > 127 ? 127 : bn);
                    atomicAdd(&HistW[bn], 1u);
                }
            }
            __syncwarp();

            // warp scan of 128-bin histogram; locate critical bin
            uint4 hv = *(const uint4*)&HistW[lane*4];
            int h0 = (int)hv.x, h1 = (int)hv.y, h2 = (int)hv.z, h3 = (int)hv.w;
            int ssum = h0 + h1 + h2 + h3;
            int incl = ssum;
            #pragma unroll
            for (int off = 1; off < 32; off <<= 1) {
                int v = __shfl_up_sync(FULLM, incl, off);
                if (lane >= off) incl += v;
            }
            int excl = incl - ssum;
            int target = 63 - c_sel;
            bool has = (excl <= target && target < incl);
            int cum = excl, bsel = lane*4;
            if (target >= cum + h0) { cum += h0; bsel++;
                if (target >= cum + h1) { cum += h1; bsel++;
                    if (target >= cum + h2) { cum += h2; bsel++; } } }
            int infoL = (bsel << 16) | cum;
            unsigned bal = __ballot_sync(FULLM, has);
            int info = __shfl_sync(FULLM, infoL, bal ? (__ffs(bal) - 1) : 31);
            if (!bal) info = 127 << 16;

            int cb = info >> 16;
            c_sel += info & 0xffff;
            int mcrit = (int)HistW[cb];

            // classification over active set
            unsigned m = actm;
            while (m) {
                int k = __ffs(m) - 1; m &= m - 1;
                int p, q;
                if (full) { p = (lane << 1) + (k >> 4); q = k & 15; }
                else      { p = lane >> 1; q = ((lane & 1) << 3) | k; }
                int a  = ((q >> 2) & 2) | ((q >> 1) & 1);
                int bq = ((q >> 1) & 2) | (q & 1);
                float d = PrsW[p][a] + PisW[p][bq];
                int bn = (int)((d - lo) * scale);
                bn = bn < 0 ? 0 : (bn > 127 ? 127 : bn);
                if (bn < cb)      { selm |= 1u << k; actm &= ~(1u << k); }
                else if (bn > cb) { actm &= ~(1u << k); }
            }
            if (mcrit <= 64 || lev == 3) break;
            float w = (hi - lo) * 0.0078125f;
            float nlo = fmaf((float)cb, w, lo);
            hi = nlo + w;
            lo = nlo;
        }

        // scan-based compaction (single warp owns counters: no atomics)
        {
            int nsel = __popc(selm), neq = __popc(actm);
            int packed = nsel | (neq << 16);
            int incl = packed;
            #pragma unroll
            for (int off = 1; off < 32; off <<= 1) {
                int v = __shfl_up_sync(FULLM, incl, off);
                if (lane >= off) incl += v;
            }
            int excl = incl - packed;
            int sb = excl & 0xffff;
            int eb = excl >> 16;

            unsigned m = selm;
            while (m) {
                int k = __ffs(m) - 1; m &= m - 1;
                int p, q;
                if (full) { p = (lane << 1) + (k >> 4); q = k & 15; }
                else      { p = lane >> 1; q = ((lane & 1) << 3) | k; }
                int a  = ((q >> 2) & 2) | ((q >> 1) & 1);
                int bq = ((q >> 1) & 2) | (q & 1);
                float d = PrsW[p][a] + PisW[p][bq];
                if (sb < 64) {
                    CdistW[nxt][sb] = d;
                    CsymW[nxt][sb]  = CsymW[cur][p] | ((unsigned)q << (4*l));
                }
                sb++;
            }
            m = actm;
            while (m) {
                int k = __ffs(m) - 1; m &= m - 1;
                int p, q;
                if (full) { p = (lane << 1) + (k >> 4); q = k & 15; }
                else      { p = lane >> 1; q = ((lane & 1) << 3) | k; }
                int a  = ((q >> 2) & 2) | ((q >> 1) & 1);
                int bq = ((q >> 1) & 2) | (q & 1);
                float d = PrsW[p][a] + PisW[p][bq];
                int idx = p*16 + q;          // reference tie-break index
                if (eb < 128)
                    EqKW[eb] = (((unsigned long long)__float_as_uint(d)) << 10)
                             | (unsigned)idx;
                eb++;
            }
            __syncwarp();

            // exact tie ranking on the critical bin
            int eqTot = __shfl_sync(FULLM, incl, 31) >> 16;
            int mm = eqTot < 128 ? eqTot : 128;
            int need = 64 - c_sel;
            for (int e = lane; e < mm; e += 32) {
                unsigned long long mykey = EqKW[e];
                int rank = 0;
                for (int j = 0; j < mm; j++) rank += (EqKW[j] < mykey);
                if (rank < need) {
                    int s = c_sel + rank;
                    if (s < 64) {
                        int idx = (int)(mykey & 1023ull);
                        int p = idx >> 4, q = idx & 15;
                        CdistW[nxt][s] = __uint_as_float((unsigned)(mykey >> 10));
                        CsymW[nxt][s]  = CsymW[cur][p] | ((unsigned)q << (4*l));
                    }
                }
            }
        }
        __syncwarp();
        cur = nxt;
    }

    // ---------------- LLR: one (layer, bit) pair per lane ----------------
    {
        int l = lane >> 2, j = lane & 3;
        float d0 = 1000000000.0f, d1 = 1000000000.0f;
        #pragma unroll 1
        for (int k = 0; k < 64; k++) {
            float d = CdistW[cur][k];
            int q = (int)((CsymW[cur][k] >> (4*l)) & 15u);
            if ((q >> (3 - j)) & 1) d1 = fminf(d1, d);
            else                    d0 = fminf(d0, d);
        }
        float llr = fminf(fmaxf(d0 - d1, -20.f), 20.f);
        g_out[b*32 + OrderW[l]*4 + j] = llr;
    }
}

extern "C" void kernel_launch(void* const* d_in, const int* in_sizes, int n_in,
                              void* d_out, int out_size)
{
    const float* yr = (const float*)d_in[0];
    const float* yi = (const float*)d_in[1];
    const float* hr = (const float*)d_in[2];
    const float* hi = (const float*)d_in[3];
    const float* sr = (const float*)d_in[4];
    const float* si = (const float*)d_in[5];
    const float* pr = (const float*)d_in[6];
    const float* pi = (const float*)d_in[7];
    int B = in_sizes[0] / 16;
    kbest_kernel<<<B / WPB, 32 * WPB>>>(yr, yi, hr, hi, sr, si, pr, pi, (float*)d_out);
}

// round 9
// speedup vs baseline: 2.5708x; 1.1263x over previous
#include <cuda_runtime.h>

// KBestDetector: B=16384, M=16 rx, S=8 streams, 16-QAM (NBPS=4), K=64.
// WARP-PER-BATCH: one warp owns one batch end-to-end. CTA = 4 warps.
// No __syncthreads anywhere; warp-synchronous throughout.
//
// Shared memory is phase-unioned per warp:
//   phase A (preamble):  Lsh (2176 B) + Hts (1152 B)
//   phase B (K-best):    Prs (1024) + Pis (1024) + Hist (512) + EqK (1024)
// Both overlay one 3584-B buffer; A is dead before B's first write
// (warp-synchronous program order). This + a 64-reg cap doubles occupancy.

#define FULLM 0xffffffffu
#define WPB 4
#define PHASE_BYTES 3584

__global__ void __launch_bounds__(128, 8) kbest_kernel(
    const float* __restrict__ g_yr, const float* __restrict__ g_yi,
    const float* __restrict__ g_hr, const float* __restrict__ g_hi,
    const float* __restrict__ g_sr, const float* __restrict__ g_si,
    const float* __restrict__ g_pr, const float* __restrict__ g_pi,
    float* __restrict__ g_out)
{
    const int lane = threadIdx.x & 31;
    const int wrp  = threadIdx.x >> 5;
    const int b    = blockIdx.x * WPB + wrp;

    __shared__ __align__(16) char Buf[WPB][PHASE_BYTES];
    __shared__ float2 Gsh[WPB][8][8];
    __shared__ float2 Csh[WPB][8][8];
    __shared__ float2 Zsh[WPB][8];
    __shared__ float2 Ybar[WPB][8];
    __shared__ int    Order[WPB][8];
    __shared__ float2 Pts[WPB][16];
    __shared__ float    Cdist[WPB][2][64];
    __shared__ unsigned Csym[WPB][2][64];

    char* bufW = Buf[wrp];
    // phase A overlays
    float2 (*LshW)[17] = (float2(*)[17])bufW;                    // 16x17x8 = 2176
    float2 (*HtsW)[9]  = (float2(*)[9])(bufW + 2176);            // 16x9x8  = 1152
    // phase B overlays
    float (*PrsW)[4] = (float(*)[4])bufW;                        // 1024
    float (*PisW)[4] = (float(*)[4])(bufW + 1024);               // 1024
    unsigned *HistW  = (unsigned*)(bufW + 2048);                 // 512
    unsigned long long *EqKW = (unsigned long long*)(bufW + 2560); // 1024

    float2 (*GshW)[8]  = Gsh[wrp];
    float2 (*CshW)[8]  = Csh[wrp];
    float2 *ZshW  = Zsh[wrp];
    float2 *YbarW = Ybar[wrp];
    int    *OrderW = Order[wrp];
    float2 *PtsW  = Pts[wrp];
    float    (*CdistW)[64] = Cdist[wrp];
    unsigned (*CsymW)[64]  = Csym[wrp];

    // ---------------- load ----------------
    for (int t = lane; t < 256; t += 32)
        LshW[t >> 4][t & 15] = make_float2(g_sr[b*256 + t], g_si[b*256 + t]);
    for (int t = lane; t < 128; t += 32)
        HtsW[t >> 3][t & 7] = make_float2(g_hr[b*128 + t], g_hi[b*128 + t]);
    if (lane < 16) {
        HtsW[lane][8] = make_float2(g_yr[b*16 + lane], g_yi[b*16 + lane]);
        PtsW[lane]    = make_float2(g_pr[lane], g_pi[lane]);
    }
    __syncwarp();

    // ---------------- Cholesky 16x16 complex (lanes 0-15) ----------------
    #pragma unroll 1
    for (int jc = 0; jc < 16; jc++) {
        float sx = 0.f, sy = 0.f;
        if (lane >= jc && lane < 16) {
            float2 a0 = LshW[lane][jc];
            sx = a0.x; sy = a0.y;
            for (int k = 0; k < jc; k++) {       // s -= L[i,k]*conj(L[jc,k])
                float2 a = LshW[lane][k], c = LshW[jc][k];
                sx -= a.x*c.x + a.y*c.y;
                sy -= a.y*c.x - a.x*c.y;
            }
        }
        float dj = __shfl_sync(FULLM, sx, jc);
        float dl = sqrtf(dj);
        if (lane == jc) LshW[lane][jc] = make_float2(dl, 0.f);
        else if (lane > jc && lane < 16) LshW[lane][jc] = make_float2(sx/dl, sy/dl);
        __syncwarp();
    }

    // ------- forward solve L X = [h | y]: two columns per pass -------
    #pragma unroll 1
    for (int cp = 0; cp < 5; cp++) {
        int c = cp*2 + (lane >> 4);
        bool valid = (c < 9);
        int r = lane & 15;
        #pragma unroll 1
        for (int i = 0; i < 16; i++) {
            float xr = 0.f, xi = 0.f;
            if (r == i && valid) {
                float2 v = HtsW[i][c];
                float dd = LshW[i][i].x;
                xr = v.x / dd; xi = v.y / dd;
                HtsW[i][c] = make_float2(xr, xi);
            }
            xr = __shfl_sync(FULLM, xr, i, 16);
            xi = __shfl_sync(FULLM, xi, i, 16);
            if (r > i && valid) {
                float2 lij = LshW[r][i];
                float2 v = HtsW[r][c];
                v.x -= lij.x*xr - lij.y*xi;
                v.y -= lij.x*xi + lij.y*xr;
                HtsW[r][c] = v;
            }
            __syncwarp();
        }
    }

    // ---------------- Gram G = ht^H ht, z = ht^H yt ----------------
    for (int t = lane; t < 72; t += 32) {
        int i = (t < 64) ? (t >> 3) : (t - 64);
        int j = (t < 64) ? (t & 7)  : 8;
        float gx = 0.f, gy = 0.f;
        #pragma unroll
        for (int m = 0; m < 16; m++) {
            float2 a = HtsW[m][i], c = HtsW[m][j];
            gx += a.x*c.x + a.y*c.y;
            gy += a.x*c.y - a.y*c.x;
        }
        if (t < 64) GshW[i][j] = make_float2(gx, gy);
        else        ZshW[i]    = make_float2(gx, gy);
    }
    __syncwarp();
    // ---- phase A buffers (Lsh, Hts) are DEAD from here on ----

    // ---------------- ordering (stable argsort of -norms) ----------------
    if (lane < 8) {
        float ni = GshW[lane][lane].x;
        int rank = 0;
        #pragma unroll
        for (int j = 0; j < 8; j++) {
            float nj = GshW[j][j].x;
            rank += (nj > ni) || (nj == ni && j < lane);
        }
        OrderW[rank] = lane;
    }
    __syncwarp();
    for (int t = lane; t < 64; t += 32)
        CshW[t >> 3][t & 7] = GshW[OrderW[t >> 3]][OrderW[t & 7]];
    if (lane < 8) YbarW[lane] = ZshW[OrderW[lane]];
    __syncwarp();

    // ------- Cholesky 8x8 of permuted Gram + solve C ybar = z_p -------
    #pragma unroll 1
    for (int jc = 0; jc < 8; jc++) {
        float sx = 0.f, sy = 0.f;
        if (lane >= jc && lane < 8) {
            float2 a0 = CshW[lane][jc]; sx = a0.x; sy = a0.y;
            for (int k = 0; k < jc; k++) {
                float2 a = CshW[lane][k], c = CshW[jc][k];
                sx -= a.x*c.x + a.y*c.y;
                sy -= a.y*c.x - a.x*c.y;
            }
        }
        float dj = __shfl_sync(FULLM, sx, jc);
        float dl = sqrtf(dj);
        if (lane == jc) CshW[lane][jc] = make_float2(dl, 0.f);
        else if (lane > jc && lane < 8) CshW[lane][jc] = make_float2(sx/dl, sy/dl);
        __syncwarp();
    }
    #pragma unroll 1
    for (int i = 0; i < 8; i++) {
        float xr = 0.f, xi = 0.f;
        if (lane == i) {
            float2 v = YbarW[i];
            float dd = CshW[i][i].x;
            xr = v.x / dd; xi = v.y / dd;
            YbarW[i] = make_float2(xr, xi);
        }
        xr = __shfl_sync(FULLM, xr, i);
        xi = __shfl_sync(FULLM, xi, i);
        if (lane > i && lane < 8) {
            float2 lij = CshW[lane][i];
            float2 v = YbarW[lane];
            v.x -= lij.x*xr - lij.y*xi;
            v.y -= lij.x*xi + lij.y*xr;
            YbarW[lane] = v;
        }
        __syncwarp();
    }

    // ---------------- layer 7: 16 initial candidates ----------------
    int cur = 0;
    if (lane < 16) {
        float r77 = CshW[7][7].x;
        float2 p = PtsW[lane];
        float rr = YbarW[7].x - r77*p.x;
        float ri = YbarW[7].y - r77*p.y;
        CdistW[0][lane] = rr*rr + ri*ri;
        CsymW[0][lane]  = (unsigned)lane << 28;
    }
    __syncwarp();

    // ---------------- layers 6..0 ----------------
    for (int l = 6; l >= 0; l--) {
        const bool full = (l != 6);
        const int nP  = full ? 64 : 16;
        const int nxt = cur ^ 1;

        // per-parent separable distance tables
        for (int p = lane; p < nP; p += 32) {
            unsigned sym = CsymW[cur][p];
            float pd = CdistW[cur][p];
            float ir = 0.f, ii = 0.f;
            for (int j = l + 1; j < 8; j++) {
                int q = (sym >> (4*j)) & 15;
                float2 c = CshW[j][l];
                float2 pt = PtsW[q];
                ir += c.x*pt.x + c.y*pt.y;
                ii += c.x*pt.y - c.y*pt.x;
            }
            float br = YbarW[l].x - ir;
            float bi = YbarW[l].y - ii;
            float rll = CshW[l][l].x;
            float4 prv, piv;
            {
                float t0 = fmaf(-rll, PtsW[0].x,  br);
                float t1 = fmaf(-rll, PtsW[2].x,  br);
                float t2 = fmaf(-rll, PtsW[8].x,  br);
                float t3 = fmaf(-rll, PtsW[10].x, br);
                prv.x = fmaf(t0, t0, pd); prv.y = fmaf(t1, t1, pd);
                prv.z = fmaf(t2, t2, pd); prv.w = fmaf(t3, t3, pd);
            }
            {
                float t0 = fmaf(-rll, PtsW[0].y, bi);
                float t1 = fmaf(-rll, PtsW[1].y, bi);
                float t2 = fmaf(-rll, PtsW[4].y, bi);
                float t3 = fmaf(-rll, PtsW[5].y, bi);
                piv.x = t0*t0; piv.y = t1*t1; piv.z = t2*t2; piv.w = t3*t3;
            }
            *(float4*)PrsW[p] = prv;
            *(float4*)PisW[p] = piv;
        }
        *(uint4*)&HistW[lane*4] = make_uint4(0u, 0u, 0u, 0u);
        __syncwarp();

        // pass 1: per-lane min + certificate payload
        float mn, Tpay;
        float4 A0, B0, A1, B1;
        if (full) {
            A0 = *(const float4*)PrsW[2*lane];     B0 = *(const float4*)PisW[2*lane];
            A1 = *(const float4*)PrsW[2*lane + 1]; B1 = *(const float4*)PisW[2*lane + 1];
            #define MIN4_(pa, B) fminf(fminf(pa + B.x, pa + B.y), fminf(pa + B.z, pa + B.w))
            float m0 = fminf(fminf(MIN4_(A0.x, B0), MIN4_(A0.y, B0)),
                             fminf(MIN4_(A0.z, B0), MIN4_(A0.w, B0)));
            float m1 = fminf(fminf(MIN4_(A1.x, B1), MIN4_(A1.y, B1)),
                             fminf(MIN4_(A1.z, B1), MIN4_(A1.w, B1)));
            mn   = fminf(m0, m1);
            Tpay = fmaxf(m0, m1);          // parent-best: certifies d_(64)
        } else {
            A0 = *(const float4*)PrsW[lane >> 1];
            B0 = *(const float4*)PisW[lane >> 1];
            float pa0 = (lane & 1) ? A0.z : A0.x;
            float pa1 = (lane & 1) ? A0.w : A0.y;
            float d0 = pa0 + B0.x, d1 = pa0 + B0.y, d2 = pa1 + B0.x, d3 = pa1 + B0.y;
            float d4 = pa0 + B0.z, d5 = pa0 + B0.w, d6 = pa1 + B0.z, d7 = pa1 + B0.w;
            mn   = fminf(fminf(fminf(d0,d1),fminf(d2,d3)), fminf(fminf(d4,d5),fminf(d6,d7)));
            Tpay = fmaxf(fmaxf(fmaxf(d0,d1),fmaxf(d2,d3)), fmaxf(fmaxf(d4,d5),fmaxf(d6,d7)));
        }
        float lo = mn, T = Tpay;
        #pragma unroll
        for (int o = 16; o; o >>= 1) {
            lo = fminf(lo, __shfl_xor_sync(FULLM, lo, o));
            T  = fmaxf(T,  __shfl_xor_sync(FULLM, T,  o));
        }
        float hi = T;
        float scale = 128.f / fmaxf(hi - lo, 1e-30f);

        // pass 2: prune (d<=T) + level-0 histogram + active mask
        unsigned actm = 0u, selm = 0u;
        #define P2_(k, pa, pb) { float d = (pa) + (pb); \
            if (d <= T) { int bn = (int)((d - lo) * scale); \
                bn = bn < 0 ? 0 : (bn > 127 ? 127 : bn); \
                atomicAdd(&HistW[bn], 1u); actm |= (1u << (k)); } }
        if (full) {
            P2_( 0, A0.x, B0.x) P2_( 1, A0.x, B0.y) P2_( 2, A0.y, B0.x) P2_( 3, A0.y, B0.y)
            P2_( 4, A0.x, B0.z) P2_( 5, A0.x, B0.w) P2_( 6, A0.y, B0.z) P2_( 7, A0.y, B0.w)
            P2_( 8, A0.z, B0.x) P2_( 9, A0.z, B0.y) P2_(10, A0.w, B0.x) P2_(11, A0.w, B0.y)
            P2_(12, A0.z, B0.z) P2_(13, A0.z, B0.w) P2_(14, A0.w, B0.z) P2_(15, A0.w, B0.w)
            P2_(16, A1.x, B1.x) P2_(17, A1.x, B1.y) P2_(18, A1.y, B1.x) P2_(19, A1.y, B1.y)
            P2_(20, A1.x, B1.z) P2_(21, A1.x, B1.w) P2_(22, A1.y, B1.z) P2_(23, A1.y, B1.w)
            P2_(24, A1.z, B1.x) P2_(25, A1.z, B1.y) P2_(26, A1.w, B1.x) P2_(27, A1.w, B1.y)
            P2_(28, A1.z, B1.z) P2_(29, A1.z, B1.w) P2_(30, A1.w, B1.z) P2_(31, A1.w, B1.w)
        } else {
            float pa0 = (lane & 1) ? A0.z : A0.x;
            float pa1 = (lane & 1) ? A0.w : A0.y;
            P2_(0, pa0, B0.x) P2_(1, pa0, B0.y) P2_(2, pa1, B0.x) P2_(3, pa1, B0.y)
            P2_(4, pa0, B0.z) P2_(5, pa0, B0.w) P2_(6, pa1, B0.z) P2_(7, pa1, B0.w)
        }

        // adaptive select loop (exact; ties via EqK)
        int c_sel = 0;
        #pragma unroll 1
        for (int lev = 0; ; lev++) {
            if (lev) {
                __syncwarp();
                *(uint4*)&HistW[lane*4] = make_uint4(0u, 0u, 0u, 0u);
                __syncwarp();
                scale = 128.f / fmaxf(hi - lo, 1e-30f);
                unsigned m = actm;
                while (m) {
                    int k = __ffs(m) - 1; m &= m - 1;
                    int p, q;
                    if (full) { p = (lane << 1) + (k >> 4); q = k & 15; }
                    else      { p = lane >> 1; q = ((lane & 1) << 3) | k; }
                    int a  = ((q >> 2) & 2) | ((q >> 1) & 1);
                    int bq = ((q >> 1) & 2) | (q & 1);
                    float d = PrsW[p][a] + PisW[p][bq];
                    int bn = (int)((d - lo) * scale);
                    bn = bn < 0 ? 0 : (bn > 127 ? 127 : bn);
                    atomicAdd(&HistW[bn], 1u);
                }
            }
            __syncwarp();

            // warp scan of 128-bin histogram; locate critical bin
            uint4 hv = *(const uint4*)&HistW[lane*4];
            int h0 = (int)hv.x, h1 = (int)hv.y, h2 = (int)hv.z, h3 = (int)hv.w;
            int ssum = h0 + h1 + h2 + h3;
            int incl = ssum;
            #pragma unroll
            for (int off = 1; off < 32; off <<= 1) {
                int v = __shfl_up_sync(FULLM, incl, off);
                if (lane >= off) incl += v;
            }
            int excl = incl - ssum;
            int target = 63 - c_sel;
            bool has = (excl <= target && target < incl);
            int cum = excl, bsel = lane*4;
            if (target >= cum + h0) { cum += h0; bsel++;
                if (target >= cum + h1) { cum += h1; bsel++;
                    if (target >= cum + h2) { cum += h2; bsel++; } } }
            int infoL = (bsel << 16) | cum;
            unsigned bal = __ballot_sync(FULLM, has);
            int info = __shfl_sync(FULLM, infoL, bal ? (__ffs(bal) - 1) : 31);
            if (!bal) info = 127 << 16;

            int cb = info >> 16;
            c_sel += info & 0xffff;
            int mcrit = (int)HistW[cb];

            // classification over active set
            unsigned m = actm;
            while (m) {
                int k = __ffs(m) - 1; m &= m - 1;
                int p, q;
                if (full) { p = (lane << 1) + (k >> 4); q = k & 15; }
                else      { p = lane >> 1; q = ((lane & 1) << 3) | k; }
                int a  = ((q >> 2) & 2) | ((q >> 1) & 1);
                int bq = ((q >> 1) & 2) | (q & 1);
                float d = PrsW[p][a] + PisW[p][bq];
                int bn = (int)((d - lo) * scale);
                bn = bn < 0 ? 0 : (bn > 127 ? 127 : bn);
                if (bn < cb)      { selm |= 1u << k; actm &= ~(1u << k); }
                else if (bn > cb) { actm &= ~(1u << k); }
            }
            if (mcrit <= 64 || lev == 3) break;
            float w = (hi - lo) * 0.0078125f;
            float nlo = fmaf((float)cb, w, lo);
            hi = nlo + w;
            lo = nlo;
        }

        // scan-based compaction (single warp owns counters: no atomics)
        {
            int nsel = __popc(selm), neq = __popc(actm);
            int packed = nsel | (neq << 16);
            int incl = packed;
            #pragma unroll
            for (int off = 1; off < 32; off <<= 1) {
                int v = __shfl_up_sync(FULLM, incl, off);
                if (lane >= off) incl += v;
            }
            int excl = incl - packed;
            int sb = excl & 0xffff;
            int eb = excl >> 16;

            unsigned m = selm;
            while (m) {
                int k = __ffs(m) - 1; m &= m - 1;
                int p, q;
                if (full) { p = (lane << 1) + (k >> 4); q = k & 15; }
                else      { p = lane >> 1; q = ((lane & 1) << 3) | k; }
                int a  = ((q >> 2) & 2) | ((q >> 1) & 1);
                int bq = ((q >> 1) & 2) | (q & 1);
                float d = PrsW[p][a] + PisW[p][bq];
                if (sb < 64) {
                    CdistW[nxt][sb] = d;
                    CsymW[nxt][sb]  = CsymW[cur][p] | ((unsigned)q << (4*l));
                }
                sb++;
            }
            m = actm;
            while (m) {
                int k = __ffs(m) - 1; m &= m - 1;
                int p, q;
                if (full) { p = (lane << 1) + (k >> 4); q = k & 15; }
                else      { p = lane >> 1; q = ((lane & 1) << 3) | k; }
                int a  = ((q >> 2) & 2) | ((q >> 1) & 1);
                int bq = ((q >> 1) & 2) | (q & 1);
                float d = PrsW[p][a] + PisW[p][bq];
                int idx = p*16 + q;          // reference tie-break index
                if (eb < 128)
                    EqKW[eb] = (((unsigned long long)__float_as_uint(d)) << 10)
                             | (unsigned)idx;
                eb++;
            }
            __syncwarp();

            // exact tie ranking on the critical bin
            int eqTot = __shfl_sync(FULLM, incl, 31) >> 16;
            int mm = eqTot < 128 ? eqTot : 128;
            int need = 64 - c_sel;
            for (int e = lane; e < mm; e += 32) {
                unsigned long long mykey = EqKW[e];
                int rank = 0;
                for (int j = 0; j < mm; j++) rank += (EqKW[j] < mykey);
                if (rank < need) {
                    int s = c_sel + rank;
                    if (s < 64) {
                        int idx = (int)(mykey & 1023ull);
                        int p = idx >> 4, q = idx & 15;
                        CdistW[nxt][s] = __uint_as_float((unsigned)(mykey >> 10));
                        CsymW[nxt][s]  = CsymW[cur][p] | ((unsigned)q << (4*l));
                    }
                }
            }
        }
        __syncwarp();
        cur = nxt;
    }

    // ---------------- LLR: one (layer, bit) pair per lane ----------------
    {
        int l = lane >> 2, j = lane & 3;
        float d0 = 1000000000.0f, d1 = 1000000000.0f;
        #pragma unroll 1
        for (int k = 0; k < 64; k++) {
            float d = CdistW[cur][k];
            int q = (int)((CsymW[cur][k] >> (4*l)) & 15u);
            if ((q >> (3 - j)) & 1) d1 = fminf(d1, d);
            else                    d0 = fminf(d0, d);
        }
        float llr = fminf(fmaxf(d0 - d1, -20.f), 20.f);
        g_out[b*32 + OrderW[l]*4 + j] = llr;
    }
}

extern "C" void kernel_launch(void* const* d_in, const int* in_sizes, int n_in,
                              void* d_out, int out_size)
{
    const float* yr = (const float*)d_in[0];
    const float* yi = (const float*)d_in[1];
    const float* hr = (const float*)d_in[2];
    const float* hi = (const float*)d_in[3];
    const float* sr = (const float*)d_in[4];
    const float* si = (const float*)d_in[5];
    const float* pr = (const float*)d_in[6];
    const float* pi = (const float*)d_in[7];
    int B = in_sizes[0] / 16;
    kbest_kernel<<<B / WPB, 32 * WPB>>>(yr, yi, hr, hi, sr, si, pr, pi, (float*)d_out);
}

// round 11
// speedup vs baseline: 2.5926x; 1.0085x over previous
#include <cuda_runtime.h>

// KBestDetector: B=16384, M=16 rx, S=8 streams, 16-QAM (NBPS=4), K=64.
// WARP-PER-BATCH, CTA = 2 warps. No __syncthreads; warp-synchronous.
//
// NOTE: chol16 / chol8 / column norms MUST keep round-9's exact summation
// order — the argsort ordering and the K-best tree are discretely sensitive
// to their rounding (round-10 lesson: split-sums => rel_err 1.8e-3).
//
//  - permuted Gram: lower triangle + Ybar computed directly from Order
//    (same inner-loop arithmetic as the full-Gram version; diag = norms)
//  - K-best: separable distances; certified prune T (full layers only);
//    exact top-64 via adaptive 128-bin select, float-threshold
//    classification (exact-equivalent), tie cleanup, scan compaction
//
// Shared memory phase-union per warp (3584 B):
//   phase A: Lsh (2176) + Hts (1152)   [dead after Csh/Ybar built]
//   phase B: Prs (1024) + Pis (1024) + Hist (512) + EqK (1024)

#define FULLM 0xffffffffu
#define WPB 2
#define PHASE_BYTES 3584

__global__ void __launch_bounds__(64, 16) kbest_kernel(
    const float* __restrict__ g_yr, const float* __restrict__ g_yi,
    const float* __restrict__ g_hr, const float* __restrict__ g_hi,
    const float* __restrict__ g_sr, const float* __restrict__ g_si,
    const float* __restrict__ g_pr, const float* __restrict__ g_pi,
    float* __restrict__ g_out)
{
    const int lane = threadIdx.x & 31;
    const int wrp  = threadIdx.x >> 5;
    const int b    = blockIdx.x * WPB + wrp;

    __shared__ __align__(16) char Buf[WPB][PHASE_BYTES];
    __shared__ float2 Csh[WPB][8][8];
    __shared__ float2 Ybar[WPB][8];
    __shared__ int    Order[WPB][8];
    __shared__ float2 Pts[WPB][16];
    __shared__ float    Cdist[WPB][2][64];
    __shared__ unsigned Csym[WPB][2][64];

    char* bufW = Buf[wrp];
    // phase A overlays
    float2 (*LshW)[17] = (float2(*)[17])bufW;                      // 2176
    float2 (*HtsW)[9]  = (float2(*)[9])(bufW + 2176);              // 1152
    // phase B overlays
    float (*PrsW)[4] = (float(*)[4])bufW;                          // 1024
    float (*PisW)[4] = (float(*)[4])(bufW + 1024);                 // 1024
    unsigned *HistW  = (unsigned*)(bufW + 2048);                   // 512
    unsigned long long *EqKW = (unsigned long long*)(bufW + 2560); // 1024

    float2 (*CshW)[8]  = Csh[wrp];
    float2 *YbarW = Ybar[wrp];
    int    *OrderW = Order[wrp];
    float2 *PtsW  = Pts[wrp];
    float    (*CdistW)[64] = Cdist[wrp];
    unsigned (*CsymW)[64]  = Csym[wrp];

    // ---------------- load ----------------
    for (int t = lane; t < 256; t += 32)
        LshW[t >> 4][t & 15] = make_float2(g_sr[b*256 + t], g_si[b*256 + t]);
    for (int t = lane; t < 128; t += 32)
        HtsW[t >> 3][t & 7] = make_float2(g_hr[b*128 + t], g_hi[b*128 + t]);
    if (lane < 16) {
        HtsW[lane][8] = make_float2(g_yr[b*16 + lane], g_yi[b*16 + lane]);
        PtsW[lane]    = make_float2(g_pr[lane], g_pi[lane]);
    }
    __syncwarp();

    // ------- Cholesky 16x16 complex (round-9 exact form) -------
    #pragma unroll 1
    for (int jc = 0; jc < 16; jc++) {
        float sx = 0.f, sy = 0.f;
        if (lane >= jc && lane < 16) {
            float2 a0 = LshW[lane][jc];
            sx = a0.x; sy = a0.y;
            for (int k = 0; k < jc; k++) {       // s -= L[i,k]*conj(L[jc,k])
                float2 a = LshW[lane][k], c = LshW[jc][k];
                sx -= a.x*c.x + a.y*c.y;
                sy -= a.y*c.x - a.x*c.y;
            }
        }
        float dj = __shfl_sync(FULLM, sx, jc);
        float dl = sqrtf(dj);
        if (lane == jc) LshW[lane][jc] = make_float2(dl, 0.f);
        else if (lane > jc && lane < 16) LshW[lane][jc] = make_float2(sx/dl, sy/dl);
        __syncwarp();
    }

    // ------- forward solve L X = [h | y]: two columns per pass -------
    #pragma unroll 1
    for (int cp = 0; cp < 5; cp++) {
        int c = cp*2 + (lane >> 4);
        bool valid = (c < 9);
        int r = lane & 15;
        #pragma unroll 1
        for (int i = 0; i < 16; i++) {
            float xr = 0.f, xi = 0.f;
            if (r == i && valid) {
                float2 v = HtsW[i][c];
                float dd = LshW[i][i].x;
                xr = v.x / dd; xi = v.y / dd;
                HtsW[i][c] = make_float2(xr, xi);
            }
            xr = __shfl_sync(FULLM, xr, i, 16);
            xi = __shfl_sync(FULLM, xi, i, 16);
            if (r > i && valid) {
                float2 lij = LshW[r][i];
                float2 v = HtsW[r][c];
                v.x -= lij.x*xr - lij.y*xi;
                v.y -= lij.x*xi + lij.y*xr;
                HtsW[r][c] = v;
            }
            __syncwarp();
        }
    }

    // ------- column norms (round-9 exact form: sequential 16 terms) -------
    if (lane < 8) {
        float nr = 0.f;
        #pragma unroll
        for (int m = 0; m < 16; m++) {
            float2 a = HtsW[m][lane];
            nr += a.x*a.x + a.y*a.y;
        }
        CdistW[1][lane] = nr;   // Cdist[1] free pre-layer-loop
    }
    __syncwarp();
    if (lane < 8) {
        float ni = CdistW[1][lane];
        int rank = 0;
        #pragma unroll
        for (int j = 0; j < 8; j++) {
            float nj = CdistW[1][j];
            rank += (nj > ni) || (nj == ni && j < lane);
        }
        OrderW[rank] = lane;
    }
    __syncwarp();

    // ------- permuted Gram: lower triangle + Ybar, directly -------
    if (lane < 8) CshW[lane][lane] = make_float2(CdistW[1][OrderW[lane]], 0.f);
    for (int t = lane; t < 36; t += 32) {
        int i, j, oi, oj;
        if (t < 28) {                 // strict lower: row i (1..7) has i entries
            int tt = t; i = 1;
            while (tt >= i) { tt -= i; i++; }
            j = tt;
            oi = OrderW[i]; oj = OrderW[j];
        } else {                      // Ybar[i] = conj-dot(col Order[i], y)
            i = t - 28; j = -1;
            oi = OrderW[i]; oj = 8;
        }
        float gx = 0.f, gy = 0.f;
        #pragma unroll
        for (int m = 0; m < 16; m++) {
            float2 a = HtsW[m][oi], c = HtsW[m][oj];
            gx += a.x*c.x + a.y*c.y;
            gy += a.x*c.y - a.y*c.x;
        }
        if (t < 28) CshW[i][j] = make_float2(gx, gy);
        else        YbarW[i]   = make_float2(gx, gy);
    }
    __syncwarp();
    // ---- phase A buffers (Lsh, Hts) are DEAD from here on ----

    // ------- Cholesky 8x8 (round-9 exact form) -------
    #pragma unroll 1
    for (int jc = 0; jc < 8; jc++) {
        float sx = 0.f, sy = 0.f;
        if (lane >= jc && lane < 8) {
            float2 a0 = CshW[lane][jc]; sx = a0.x; sy = a0.y;
            for (int k = 0; k < jc; k++) {
                float2 a = CshW[lane][k], c = CshW[jc][k];
                sx -= a.x*c.x + a.y*c.y;
                sy -= a.y*c.x - a.x*c.y;
            }
        }
        float dj = __shfl_sync(FULLM, sx, jc);
        float dl = sqrtf(dj);
        if (lane == jc) CshW[lane][jc] = make_float2(dl, 0.f);
        else if (lane > jc && lane < 8) CshW[lane][jc] = make_float2(sx/dl, sy/dl);
        __syncwarp();
    }
    // ------- solve C ybar = z_p -------
    #pragma unroll 1
    for (int i = 0; i < 8; i++) {
        float xr = 0.f, xi = 0.f;
        if (lane == i) {
            float2 v = YbarW[i];
            float dd = CshW[i][i].x;
            xr = v.x / dd; xi = v.y / dd;
            YbarW[i] = make_float2(xr, xi);
        }
        xr = __shfl_sync(FULLM, xr, i);
        xi = __shfl_sync(FULLM, xi, i);
        if (lane > i && lane < 8) {
            float2 lij = CshW[lane][i];
            float2 v = YbarW[lane];
            v.x -= lij.x*xr - lij.y*xi;
            v.y -= lij.x*xi + lij.y*xr;
            YbarW[lane] = v;
        }
        __syncwarp();
    }

    // ---------------- layer 7: 16 initial candidates ----------------
    int cur = 0;
    if (lane < 16) {
        float r77 = CshW[7][7].x;
        float2 p = PtsW[lane];
        float rr = YbarW[7].x - r77*p.x;
        float ri = YbarW[7].y - r77*p.y;
        CdistW[0][lane] = rr*rr + ri*ri;
        CsymW[0][lane]  = (unsigned)lane << 28;
    }
    __syncwarp();

    // ---------------- layers 6..0 ----------------
    for (int l = 6; l >= 0; l--) {
        const bool full = (l != 6);
        const int nP  = full ? 64 : 16;
        const int nxt = cur ^ 1;

        // per-parent separable distance tables
        for (int p = lane; p < nP; p += 32) {
            unsigned sym = CsymW[cur][p];
            float pd = CdistW[cur][p];
            float ir = 0.f, ii = 0.f;
            for (int j = l + 1; j < 8; j++) {
                int q = (sym >> (4*j)) & 15;
                float2 c = CshW[j][l];
                float2 pt = PtsW[q];
                ir += c.x*pt.x + c.y*pt.y;
                ii += c.x*pt.y - c.y*pt.x;
            }
            float br = YbarW[l].x - ir;
            float bi = YbarW[l].y - ii;
            float rll = CshW[l][l].x;
            float4 prv, piv;
            {
                float t0 = fmaf(-rll, PtsW[0].x,  br);
                float t1 = fmaf(-rll, PtsW[2].x,  br);
                float t2 = fmaf(-rll, PtsW[8].x,  br);
                float t3 = fmaf(-rll, PtsW[10].x, br);
                prv.x = fmaf(t0, t0, pd); prv.y = fmaf(t1, t1, pd);
                prv.z = fmaf(t2, t2, pd); prv.w = fmaf(t3, t3, pd);
            }
            {
                float t0 = fmaf(-rll, PtsW[0].y, bi);
                float t1 = fmaf(-rll, PtsW[1].y, bi);
                float t2 = fmaf(-rll, PtsW[4].y, bi);
                float t3 = fmaf(-rll, PtsW[5].y, bi);
                piv.x = t0*t0; piv.y = t1*t1; piv.z = t2*t2; piv.w = t3*t3;
            }
            *(float4*)PrsW[p] = prv;
            *(float4*)PisW[p] = piv;
        }
        *(uint4*)&HistW[lane*4] = make_uint4(0u, 0u, 0u, 0u);
        __syncwarp();

        // pass 1: per-lane min + certificate payload
        float mn, Tpay;
        float4 A0, B0, A1, B1;
        if (full) {
            A0 = *(const float4*)PrsW[2*lane];     B0 = *(const float4*)PisW[2*lane];
            A1 = *(const float4*)PrsW[2*lane + 1]; B1 = *(const float4*)PisW[2*lane + 1];
            #define MIN4_(pa, B) fminf(fminf(pa + B.x, pa + B.y), fminf(pa + B.z, pa + B.w))
            float m0 = fminf(fminf(MIN4_(A0.x, B0), MIN4_(A0.y, B0)),
                             fminf(MIN4_(A0.z, B0), MIN4_(A0.w, B0)));
            float m1 = fminf(fminf(MIN4_(A1.x, B1), MIN4_(A1.y, B1)),
                             fminf(MIN4_(A1.z, B1), MIN4_(A1.w, B1)));
            mn   = fminf(m0, m1);
            Tpay = fmaxf(m0, m1);          // parent-best: certifies d_(64)
        } else {
            A0 = *(const float4*)PrsW[lane >> 1];
            B0 = *(const float4*)PisW[lane >> 1];
            float pa0 = (lane & 1) ? A0.z : A0.x;
            float pa1 = (lane & 1) ? A0.w : A0.y;
            float d0 = pa0 + B0.x, d1 = pa0 + B0.y, d2 = pa1 + B0.x, d3 = pa1 + B0.y;
            float d4 = pa0 + B0.z, d5 = pa0 + B0.w, d6 = pa1 + B0.z, d7 = pa1 + B0.w;
            mn   = fminf(fminf(fminf(d0,d1),fminf(d2,d3)), fminf(fminf(d4,d5),fminf(d6,d7)));
            Tpay = fmaxf(fmaxf(fmaxf(d0,d1),fmaxf(d2,d3)), fmaxf(fmaxf(d4,d5),fmaxf(d6,d7)));
        }
        float lo = mn, T = Tpay;
        #pragma unroll
        for (int o = 16; o; o >>= 1) {
            lo = fminf(lo, __shfl_xor_sync(FULLM, lo, o));
            T  = fmaxf(T,  __shfl_xor_sync(FULLM, T,  o));
        }
        float hi = T;
        float scale = 128.f / fmaxf(hi - lo, 1e-30f);

        // pass 2: prune (d<=T) + level-0 histogram + active mask
        unsigned actm = 0u, selm = 0u;
        #define P2_(k, pa, pb) { float d = (pa) + (pb); \
            if (d <= T) { int bn = (int)((d - lo) * scale); \
                bn = bn > 127 ? 127 : bn; \
                atomicAdd(&HistW[bn], 1u); actm |= (1u << (k)); } }
        if (full) {
            P2_( 0, A0.x, B0.x) P2_( 1, A0.x, B0.y) P2_( 2, A0.y, B0.x) P2_( 3, A0.y, B0.y)
            P2_( 4, A0.x, B0.z) P2_( 5, A0.x, B0.w) P2_( 6, A0.y, B0.z) P2_( 7, A0.y, B0.w)
            P2_( 8, A0.z, B0.x) P2_( 9, A0.z, B0.y) P2_(10, A0.w, B0.x) P2_(11, A0.w, B0.y)
            P2_(12, A0.z, B0.z) P2_(13, A0.z, B0.w) P2_(14, A0.w, B0.z) P2_(15, A0.w, B0.w)
            P2_(16, A1.x, B1.x) P2_(17, A1.x, B1.y) P2_(18, A1.y, B1.x) P2_(19, A1.y, B1.y)
            P2_(20, A1.x, B1.z) P2_(21, A1.x, B1.w) P2_(22, A1.y, B1.z) P2_(23, A1.y, B1.w)
            P2_(24, A1.z, B1.x) P2_(25, A1.z, B1.y) P2_(26, A1.w, B1.x) P2_(27, A1.w, B1.y)
            P2_(28, A1.z, B1.z) P2_(29, A1.z, B1.w) P2_(30, A1.w, B1.z) P2_(31, A1.w, B1.w)
        } else {
            float pa0 = (lane & 1) ? A0.z : A0.x;
            float pa1 = (lane & 1) ? A0.w : A0.y;
            P2_(0, pa0, B0.x) P2_(1, pa0, B0.y) P2_(2, pa1, B0.x) P2_(3, pa1, B0.y)
            P2_(4, pa0, B0.z) P2_(5, pa0, B0.w) P2_(6, pa1, B0.z) P2_(7, pa1, B0.w)
        }

        // adaptive select loop (exact; ties via EqK)
        int c_sel = 0;
        #pragma unroll 1
        for (int lev = 0; ; lev++) {
            if (lev) {
                __syncwarp();
                *(uint4*)&HistW[lane*4] = make_uint4(0u, 0u, 0u, 0u);
                __syncwarp();
                scale = 128.f / fmaxf(hi - lo, 1e-30f);
                unsigned m = actm;
                while (m) {
                    int k = __ffs(m) - 1; m &= m - 1;
                    int p, q;
                    if (full) { p = (lane << 1) + (k >> 4); q = k & 15; }
                    else      { p = lane >> 1; q = ((lane & 1) << 3) | k; }
                    int a  = ((q >> 2) & 2) | ((q >> 1) & 1);
                    int bq = ((q >> 1) & 2) | (q & 1);
                    float d = PrsW[p][a] + PisW[p][bq];
                    int bn = (int)((d - lo) * scale);
                    bn = bn < 0 ? 0 : (bn > 127 ? 127 : bn);
                    atomicAdd(&HistW[bn], 1u);
                }
            }
            __syncwarp();

            // warp scan of 128-bin histogram; locate critical bin
            uint4 hv = *(const uint4*)&HistW[lane*4];
            int h0 = (int)hv.x, h1 = (int)hv.y, h2 = (int)hv.z, h3 = (int)hv.w;
            int ssum = h0 + h1 + h2 + h3;
            int incl = ssum;
            #pragma unroll
            for (int off = 1; off < 32; off <<= 1) {
                int v = __shfl_up_sync(FULLM, incl, off);
                if (lane >= off) incl += v;
            }
            int excl = incl - ssum;
            int target = 63 - c_sel;
            bool has = (excl <= target && target < incl);
            int cum = excl, bsel = lane*4;
            if (target >= cum + h0) { cum += h0; bsel++;
                if (target >= cum + h1) { cum += h1; bsel++;
                    if (target >= cum + h2) { cum += h2; bsel++; } } }
            int infoL = (bsel << 16) | cum;
            unsigned bal = __ballot_sync(FULLM, has);
            int info = __shfl_sync(FULLM, infoL, bal ? (__ffs(bal) - 1) : 31);
            if (!bal) info = 127 << 16;

            int cb = info >> 16;
            c_sel += info & 0xffff;
            int mcrit = (int)HistW[cb];

            // classification via float thresholds (exact-equivalent to int bins)
            float cbF   = (float)cb;
            float cbHiF = (cb == 127) ? 3.0e38f : (float)(cb + 1);
            unsigned m = actm;
            while (m) {
                int k = __ffs(m) - 1; m &= m - 1;
                int p, q;
                if (full) { p = (lane << 1) + (k >> 4); q = k & 15; }
                else      { p = lane >> 1; q = ((lane & 1) << 3) | k; }
                int a  = ((q >> 2) & 2) | ((q >> 1) & 1);
                int bq = ((q >> 1) & 2) | (q & 1);
                float d = PrsW[p][a] + PisW[p][bq];
                float x = fmaxf((d - lo) * scale, 0.f);
                if (x < cbF)         { selm |= 1u << k; actm &= ~(1u << k); }
                else if (x >= cbHiF) { actm &= ~(1u << k); }
            }
            if (mcrit <= 64 || lev == 3) break;
            float w = (hi - lo) * 0.0078125f;
            float nlo = fmaf((float)cb, w, lo);
            hi = nlo + w;
            lo = nlo;
        }

        // scan-based compaction (single warp owns counters: no atomics)
        {
            int nsel = __popc(selm), neq = __popc(actm);
            int packed = nsel | (neq << 16);
            int incl = packed;
            #pragma unroll
            for (int off = 1; off < 32; off <<= 1) {
                int v = __shfl_up_sync(FULLM, incl, off);
                if (lane >= off) incl += v;
            }
            int excl = incl - packed;
            int sb = excl & 0xffff;
            int eb = excl >> 16;

            unsigned m = selm;
            while (m) {
                int k = __ffs(m) - 1; m &= m - 1;
                int p, q;
                if (full) { p = (lane << 1) + (k >> 4); q = k & 15; }
                else      { p = lane >> 1; q = ((lane & 1) << 3) | k; }
                int a  = ((q >> 2) & 2) | ((q >> 1) & 1);
                int bq = ((q >> 1) & 2) | (q & 1);
                float d = PrsW[p][a] + PisW[p][bq];
                if (sb < 64) {
                    CdistW[nxt][sb] = d;
                    CsymW[nxt][sb]  = CsymW[cur][p] | ((unsigned)q << (4*l));
                }
                sb++;
            }
            m = actm;
            while (m) {
                int k = __ffs(m) - 1; m &= m - 1;
                int p, q;
                if (full) { p = (lane << 1) + (k >> 4); q = k & 15; }
                else      { p = lane >> 1; q = ((lane & 1) << 3) | k; }
                int a  = ((q >> 2) & 2) | ((q >> 1) & 1);
                int bq = ((q >> 1) & 2) | (q & 1);
                float d = PrsW[p][a] + PisW[p][bq];
                int idx = p*16 + q;          // reference tie-break index
                if (eb < 128)
                    EqKW[eb] = (((unsigned long long)__float_as_uint(d)) << 10)
                             | (unsigned)idx;
                eb++;
            }
            __syncwarp();

            // exact tie ranking on the critical bin
            int eqTot = __shfl_sync(FULLM, incl, 31) >> 16;
            int mm = eqTot < 128 ? eqTot : 128;
            int need = 64 - c_sel;
            for (int e = lane; e < mm; e += 32) {
                unsigned long long mykey = EqKW[e];
                int rank = 0;
                for (int j = 0; j < mm; j++) rank += (EqKW[j] < mykey);
                if (rank < need) {
                    int s = c_sel + rank;
                    if (s < 64) {
                        int idx = (int)(mykey & 1023ull);
                        int p = idx >> 4, q = idx & 15;
                        CdistW[nxt][s] = __uint_as_float((unsigned)(mykey >> 10));
                        CsymW[nxt][s]  = CsymW[cur][p] | ((unsigned)q << (4*l));
                    }
                }
            }
        }
        __syncwarp();
        cur = nxt;
    }

    // ---------------- LLR: one (layer, bit) pair per lane ----------------
    {
        int l = lane >> 2, j = lane & 3;
        float d0 = 1000000000.0f, d1 = 1000000000.0f;
        #pragma unroll 1
        for (int k = 0; k < 64; k++) {
            float d = CdistW[cur][k];
            int q = (int)((CsymW[cur][k] >> (4*l)) & 15u);
            if ((q >> (3 - j)) & 1) d1 = fminf(d1, d);
            else                    d0 = fminf(d0, d);
        }
        float llr = fminf(fmaxf(d0 - d1, -20.f), 20.f);
        g_out[b*32 + OrderW[l]*4 + j] = llr;
    }
}

extern "C" void kernel_launch(void* const* d_in, const int* in_sizes, int n_in,
                              void* d_out, int out_size)
{
    const float* yr = (const float*)d_in[0];
    const float* yi = (const float*)d_in[1];
    const float* hr = (const float*)d_in[2];
    const float* hi = (const float*)d_in[3];
    const float* sr = (const float*)d_in[4];
    const float* si = (const float*)d_in[5];
    const float* pr = (const float*)d_in[6];
    const float* pi = (const float*)d_in[7];
    int B = in_sizes[0] / 16;
    kbest_kernel<<<B / WPB, 32 * WPB>>>(yr, yi, hr, hi, sr, si, pr, pi, (float*)d_out);
}